// round 14
// baseline (speedup 1.0000x reference)
#include <cuda_runtime.h>
#include <cuda_fp16.h>
#include <math.h>

#define NB 16
#define NN 48
#define HID 64
#define MSG 64
#define EDGE 16
#define NL 128
#define TGT 128
#define NE (NB*NN*NN)    // 36864 edges
#define NNODE (NB*NN)    // 768 nodes

// -------- device scratch (static; no allocation) --------
__device__ uint4 d_SPh[3*32*64];     // fp16 SP: [sel][cq2][m] = 8 halfs
__device__ float2 d_SPb[3*64];       // bias prefix row [sel][m] (fp32)
__device__ uint4 d_wihh[8*192];      // fp16 wih: [kq2][gc]
__device__ uint4 d_whhh[8*192];      // fp16 whh
__device__ __half d_w1t[NL*NL];      // msg_w1 transposed [n][k], fp16
__device__ __half d_w0t[NL*EDGE];    // msg_w0 transposed [n][k], fp16
__device__ __half d_r2h[NE*NL];      // relu2 fp16, TRANSPOSED: [(b*48+j)*48+i][c]
__device__ float d_gT[NNODE*NN];     // g transposed: [b*48+j][i]
__device__ float d_hf[NNODE*HID];    // h_first (normal layout)
__device__ float d_hA[NNODE*HID];
__device__ float d_hB[NNODE*HID];
__device__ float d_hfT[HID*NNODE];   // transposed: [c][node]
__device__ float d_hAT[HID*NNODE];
__device__ float d_hBT[HID*NNODE];
__device__ float d_gh[NNODE*192];    // pipelined hidden gates (incl. bhh)
__device__ float d_mask[NNODE];
__device__ float d_tmp[NNODE*TGT];
// readout weights, fp16-packed over k-octets: [kq2][c] = 8 halfs
__device__ uint4 d_q0w0h[16*128];
__device__ uint4 d_q0w1h[16*128];
__device__ uint4 d_q0w2h[16*128];
__device__ uint4 d_q1w0h[8*128];
__device__ uint4 d_q1w1h[16*128];
__device__ uint4 d_q1w2h[16*128];

#define MMA_F16(c0,c1,c2,c3,a0,a1,a2,a3,b0,b1) \
  asm volatile("mma.sync.aligned.m16n8k16.row.col.f32.f16.f16.f32 " \
    "{%0,%1,%2,%3},{%4,%5,%6,%7},{%8,%9},{%0,%1,%2,%3};" \
    : "+f"(c0),"+f"(c1),"+f"(c2),"+f"(c3) \
    : "r"(a0),"r"(a1),"r"(a2),"r"(a3),"r"(b0),"r"(b1))

// 8-half dot: acc += sum_q tofloat(a[q])*tofloat(b[q])
__device__ __forceinline__ void dot8h(float& acc, uint4 araw, uint4 braw) {
    __half2* ap = (__half2*)&araw;
    __half2* bp = (__half2*)&braw;
    #pragma unroll
    for (int q = 0; q < 4; ++q) {
        float2 a = __half22float2(ap[q]);
        float2 b = __half22float2(bp[q]);
        acc += a.x*b.x + a.y*b.y;
    }
}

// readout fp16-weight step: 8 k-values per uint4, 4 nodes wide
__device__ __forceinline__ void ro_step(float4& acc, uint4 raw, const float4* xv) {
    __half2* hp = (__half2*)&raw;
    #pragma unroll
    for (int q = 0; q < 4; ++q) {
        float2 w = __half22float2(hp[q]);
        float4 xa = xv[2*q], xb = xv[2*q+1];
        acc.x += w.x*xa.x + w.y*xb.x;
        acc.y += w.x*xa.y + w.y*xb.y;
        acc.z += w.x*xa.z + w.y*xb.z;
        acc.w += w.x*xa.w + w.y*xb.w;
    }
}

// -------- mega-prep (unchanged from R13) --------
__global__ void __launch_bounds__(192) megaprep_kernel(
        const float* __restrict__ w2, const float* __restrict__ b2,
        const float* __restrict__ wih, const float* __restrict__ whh,
        const float* __restrict__ bhh,
        const float* __restrict__ w1, const float* __restrict__ w0,
        const float* __restrict__ h0, const float* __restrict__ g,
        const float* __restrict__ r0w0, const float* __restrict__ r0w1,
        const float* __restrict__ r0w2, const float* __restrict__ r1w0,
        const float* __restrict__ r1w1, const float* __restrict__ r1w2) {
    int blk = blockIdx.x;
    int t = threadIdx.x;
    if (blk < 128) {
        if (t < 64) {
            int c = blk, m = t;
            const float* p = w2 + c*4096 + m*64;
            float acc = 0.f, s16 = 0.f, s32 = 0.f, s48 = 0.f;
            #pragma unroll
            for (int h = 0; h < 64; ++h) {
                acc += p[h];
                if (h == 15) s16 = acc;
                if (h == 31) s32 = acc;
                if (h == 47) s48 = acc;
            }
            int cq2 = c >> 2, pos = (c & 3)*2;
            __half* base = (__half*)d_SPh;
            base[(((0*32 + cq2)*64 + m))*8 + pos    ] = __float2half(s16);
            base[(((0*32 + cq2)*64 + m))*8 + pos + 1] = __float2half(acc - s16);
            base[(((1*32 + cq2)*64 + m))*8 + pos    ] = __float2half(s32);
            base[(((1*32 + cq2)*64 + m))*8 + pos + 1] = __float2half(acc - s32);
            base[(((2*32 + cq2)*64 + m))*8 + pos    ] = __float2half(s48);
            base[(((2*32 + cq2)*64 + m))*8 + pos + 1] = __float2half(acc - s48);
        }
    } else if (blk == 128) {
        if (t < 64) {
            int m = t;
            const float* q = b2 + m*64;
            float a = 0.f, t16 = 0.f, t32 = 0.f, t48 = 0.f;
            #pragma unroll
            for (int h = 0; h < 64; ++h) {
                a += q[h];
                if (h == 15) t16 = a;
                if (h == 31) t32 = a;
                if (h == 47) t48 = a;
            }
            d_SPb[0*64+m] = make_float2(t16, a - t16);
            d_SPb[1*64+m] = make_float2(t32, a - t32);
            d_SPb[2*64+m] = make_float2(t48, a - t48);
        }
    } else if (blk < 137) {
        int kq2 = blk - 129;
        __align__(16) __half hb[8];
        #pragma unroll
        for (int q = 0; q < 8; ++q) hb[q] = __float2half(wih[t*64 + 8*kq2 + q]);
        d_wihh[kq2*192 + t] = *(uint4*)hb;
    } else if (blk < 145) {
        int kq2 = blk - 137;
        __align__(16) __half hb[8];
        #pragma unroll
        for (int q = 0; q < 8; ++q) hb[q] = __float2half(whh[t*64 + 8*kq2 + q]);
        d_whhh[kq2*192 + t] = *(uint4*)hb;
    } else if (blk < 151) {
        int mat = blk - 145;
        const float* src; uint4* dst; int nkq2;
        if (mat == 0)      { src = r0w0; dst = d_q0w0h; nkq2 = 16; }
        else if (mat == 1) { src = r0w1; dst = d_q0w1h; nkq2 = 16; }
        else if (mat == 2) { src = r0w2; dst = d_q0w2h; nkq2 = 16; }
        else if (mat == 3) { src = r1w0; dst = d_q1w0h; nkq2 = 8; }
        else if (mat == 4) { src = r1w1; dst = d_q1w1h; nkq2 = 16; }
        else               { src = r1w2; dst = d_q1w2h; nkq2 = 16; }
        int total = nkq2 * 128;
        for (int idx = t; idx < total; idx += 192) {
            int kq2 = idx >> 7, c = idx & 127;
            __align__(16) __half hb[8];
            #pragma unroll
            for (int q = 0; q < 8; ++q)
                hb[q] = __float2half(src[(8*kq2+q)*128 + c]);
            dst[idx] = *(uint4*)hb;
        }
    } else if (blk < 407) {
        int nb = blk - 151;
        int node = nb*3 + t/64;
        int c = t & 63;
        __shared__ float red[192];
        float v = (c < 32) ? h0[node*32 + c] : 0.f;
        d_hf[node*64 + c] = v;
        d_hfT[c*768 + node] = v;
        red[t] = v;
        __syncthreads();
        if (c == 0) {
            float s = 0.f;
            int b0 = (t/64)*64;
            #pragma unroll
            for (int i = 0; i < 32; ++i) s += red[b0 + i];
            d_mask[node] = (s > 0.f) ? 1.f : 0.f;
        }
        int gc = t;
        float bh = bhh[gc];
        #pragma unroll
        for (int nn = 0; nn < 3; ++nn) {
            float acc = 0.f;
            #pragma unroll 4
            for (int kq = 0; kq < 16; ++kq) {
                float4 w = *(const float4*)&whh[gc*64 + 4*kq];
                acc += w.x*red[nn*64 + 4*kq]   + w.y*red[nn*64 + 4*kq+1]
                     + w.z*red[nn*64 + 4*kq+2] + w.w*red[nn*64 + 4*kq+3];
            }
            d_gh[(nb*3 + nn)*192 + gc] = acc + bh;
        }
    } else if (blk < 423) {
        int base = (blk - 407)*2304;
        for (int r = t; r < 2304; r += 192) {
            int gidx = base + r;
            int bj = gidx / 48, i = gidx % 48;
            int b = bj / 48, j = bj % 48;
            d_gT[gidx] = g[(b*48 + i)*48 + j];
        }
    } else if (blk < 487) {
        int base = (blk - 423)*256;
        for (int idx = t; idx < 256; idx += 192) {
            int i = base + idx;
            int n = i >> 7, k = i & 127;
            d_w1t[i] = __float2half(w1[k*128 + n]);
        }
    } else {
        int base = (blk - 487)*256;
        for (int idx = t; idx < 256; idx += 192) {
            int i = base + idx;
            int n = i >> 4, k = i & 15;
            d_w0t[i] = __float2half(w0[k*128 + n]);
        }
    }
}

// -------- edge MLP via fp16 tensor cores (unchanged from R13) --------
#define RELU2_SMEM ((128*136*2 + 128*16*2)*2 + 256*4)
__global__ void __launch_bounds__(256) relu2_kernel(const float* __restrict__ e,
        const float* __restrict__ b0, const float* __restrict__ b1) {
    extern __shared__ char smem_raw[];
    __half* W1H = (__half*)smem_raw;
    __half* X1H = W1H + 128*136;
    __half* ESH = X1H + 128*136;
    __half* W0H = ESH + 128*16;
    float* B0S = (float*)(W0H + 128*16);
    float* B1S = B0S + 128;
    int t = threadIdx.x;
    int row0 = blockIdx.x * 128;

    {
        const uint4* w1v = (const uint4*)d_w1t;
        for (int idx = t; idx < 2048; idx += 256) {
            int n = idx >> 4, kq = idx & 15;
            *(uint4*)&W1H[n*136 + kq*8] = __ldg(&w1v[idx]);
        }
        const float4* ev = (const float4*)(e + row0*16);
        for (int idx = t; idx < 512; idx += 256) {
            float4 x = __ldg(&ev[idx]);
            int r = idx >> 2, kq = idx & 3;
            uint2 u;
            __half2 h0 = __floats2half2_rn(x.x, x.y);
            __half2 h1 = __floats2half2_rn(x.z, x.w);
            u.x = *(unsigned*)&h0; u.y = *(unsigned*)&h1;
            *(uint2*)&ESH[r*16 + kq*4] = u;
        }
        const uint4* w0v = (const uint4*)d_w0t;
        if (t < 256) {
            int n = t >> 1, hq = t & 1;
            *(uint4*)&W0H[n*16 + hq*8] = __ldg(&w0v[t]);
        }
        if (t < 128) { B0S[t] = b0[t]; B1S[t] = b1[t]; }
    }
    __syncthreads();

    int lane = t & 31, warp = t >> 5;
    int rbase = warp * 16;
    int grp = lane >> 2, tig = lane & 3;

    float acc[16][4];
    #pragma unroll
    for (int nt = 0; nt < 16; ++nt) {
        float bv0 = B0S[nt*8 + 2*tig], bv1 = B0S[nt*8 + 2*tig + 1];
        acc[nt][0] = bv0; acc[nt][1] = bv1; acc[nt][2] = bv0; acc[nt][3] = bv1;
    }
    {
        unsigned a0 = *(unsigned*)&ESH[(rbase+grp  )*16 + 2*tig];
        unsigned a1 = *(unsigned*)&ESH[(rbase+grp+8)*16 + 2*tig];
        unsigned a2 = *(unsigned*)&ESH[(rbase+grp  )*16 + 8 + 2*tig];
        unsigned a3 = *(unsigned*)&ESH[(rbase+grp+8)*16 + 8 + 2*tig];
        #pragma unroll
        for (int nt = 0; nt < 16; ++nt) {
            unsigned bb0 = *(unsigned*)&W0H[(nt*8+grp)*16 + 2*tig];
            unsigned bb1 = *(unsigned*)&W0H[(nt*8+grp)*16 + 8 + 2*tig];
            MMA_F16(acc[nt][0],acc[nt][1],acc[nt][2],acc[nt][3],a0,a1,a2,a3,bb0,bb1);
        }
    }
    #pragma unroll
    for (int nt = 0; nt < 16; ++nt) {
        __half2 lo = __floats2half2_rn(fmaxf(acc[nt][0],0.f), fmaxf(acc[nt][1],0.f));
        __half2 hi = __floats2half2_rn(fmaxf(acc[nt][2],0.f), fmaxf(acc[nt][3],0.f));
        *(__half2*)&X1H[(rbase+grp  )*136 + nt*8 + 2*tig] = lo;
        *(__half2*)&X1H[(rbase+grp+8)*136 + nt*8 + 2*tig] = hi;
    }
    __syncthreads();

    #pragma unroll
    for (int nt = 0; nt < 16; ++nt) {
        float bv0 = B1S[nt*8 + 2*tig], bv1 = B1S[nt*8 + 2*tig + 1];
        acc[nt][0] = bv0; acc[nt][1] = bv1; acc[nt][2] = bv0; acc[nt][3] = bv1;
    }
    #pragma unroll
    for (int kt = 0; kt < 8; ++kt) {
        unsigned a0 = *(unsigned*)&X1H[(rbase+grp  )*136 + kt*16 + 2*tig];
        unsigned a1 = *(unsigned*)&X1H[(rbase+grp+8)*136 + kt*16 + 2*tig];
        unsigned a2 = *(unsigned*)&X1H[(rbase+grp  )*136 + kt*16 + 8 + 2*tig];
        unsigned a3 = *(unsigned*)&X1H[(rbase+grp+8)*136 + kt*16 + 8 + 2*tig];
        #pragma unroll
        for (int nt = 0; nt < 16; ++nt) {
            unsigned bb0 = *(unsigned*)&W1H[(nt*8+grp)*136 + kt*16 + 2*tig];
            unsigned bb1 = *(unsigned*)&W1H[(nt*8+grp)*136 + kt*16 + 8 + 2*tig];
            MMA_F16(acc[nt][0],acc[nt][1],acc[nt][2],acc[nt][3],a0,a1,a2,a3,bb0,bb1);
        }
    }
    __syncthreads();

    __half2* H = (__half2*)X1H;
    #pragma unroll
    for (int nt = 0; nt < 16; ++nt) {
        H[(rbase+grp  )*68 + nt*4 + tig] =
            __floats2half2_rn(fmaxf(acc[nt][0],0.f), fmaxf(acc[nt][1],0.f));
        H[(rbase+grp+8)*68 + nt*4 + tig] =
            __floats2half2_rn(fmaxf(acc[nt][2],0.f), fmaxf(acc[nt][3],0.f));
    }
    __syncthreads();
    for (int idx = t; idx < 2048; idx += 256) {
        int r = idx >> 4, chunk = idx & 15;
        int row = row0 + r;
        int b = row / 2304; int rem = row - b*2304;
        int i = rem / 48;   int j = rem - i*48;
        uint4 v = *(const uint4*)((const char*)X1H + (size_t)r*272 + chunk*16);
        *(uint4*)(d_r2h + (size_t)((b*48 + j)*48 + i)*128 + chunk*8) = v;
    }
}

// -------- fused layer: fp16-packed intermediates + gh prefetch --------
__global__ void __launch_bounds__(192) layer_kernel(int inbuf, int outbuf, int last,
        const float* __restrict__ bih, const float* __restrict__ bhh) {
    const float* h_in   = (inbuf  == 0) ? d_hf  : ((inbuf  == 1) ? d_hA  : d_hB);
    const float* h_inT  = (inbuf  == 0) ? d_hfT : ((inbuf  == 1) ? d_hAT : d_hBT);
    float*       h_out  = (outbuf == 1) ? d_hA  : d_hB;
    float*       h_outT = (outbuf == 1) ? d_hAT : d_hBT;
    int j = blockIdx.x; int b = blockIdx.y;
    int t = threadIdx.x;
    int bj = b*48 + j;
    int k0 = (4*j)/3;
    int a64 = (16*j) % 48;
    int sel = (48 - a64)/16 - 1;

    __shared__ float a_s[48][2];
    __shared__ float hold[64];
    __shared__ float4 Pp[4][64];
    __shared__ uint4 PqH4[32];        // fp16 P: [cq2] = 8 halfs (P0,P1 for 4 ch)
    __shared__ float part[2][64];
    __shared__ uint4 aggH4[8];        // fp16 agg: [kq2] = 8 halfs
    __shared__ float gis[192];
    __shared__ uint4 hnH4[8];         // fp16 hnew
    __shared__ float ghp[192];        // prefetched hidden gates
    __shared__ float Qs[2];
    __shared__ float maskS;

    // ---- Phase A: gathers + gh/mask prefetch ----
    ghp[t] = __ldg(&d_gh[bj*192 + t]);
    if (t < 96) {
        int s = t / 48, i = t % 48;
        float hv = __ldg(&h_inT[(k0+s)*768 + b*48 + i]);
        float gv = __ldg(&d_gT[bj*48 + i]);
        a_s[i][s] = gv * hv;
    } else if (t < 160) {
        int c = t - 96;
        hold[c] = h_in[bj*64 + c];
    } else if (t == 160) {
        maskS = d_mask[bj];
    }
    __syncthreads();

    // ---- Phase B: P partials, 32 ch-quads x 4 i-groups; Q on [128,130) ----
    if (t < 128) {
        int tq = t & 31, ig = t >> 5;
        const uint2* r2p = (const uint2*)(d_r2h + (size_t)bj*6144) + tq;
        float p00=0.f,p01=0.f,p02=0.f,p03=0.f;
        float p10=0.f,p11=0.f,p12=0.f,p13=0.f;
        int ibeg = ig*12;
        #pragma unroll
        for (int i = ibeg; i < ibeg + 12; ++i) {
            uint2 raw = __ldg(&r2p[i*32]);
            float2 v0 = __half22float2(*(__half2*)&raw.x);
            float2 v1 = __half22float2(*(__half2*)&raw.y);
            float2 aa = *(float2*)&a_s[i][0];
            p00 += aa.x*v0.x; p01 += aa.x*v0.y; p02 += aa.x*v1.x; p03 += aa.x*v1.y;
            p10 += aa.y*v0.x; p11 += aa.y*v0.y; p12 += aa.y*v1.x; p13 += aa.y*v1.y;
        }
        Pp[ig][2*tq]   = make_float4(p00, p10, p01, p11);
        Pp[ig][2*tq+1] = make_float4(p02, p12, p03, p13);
    } else if (t < 130) {
        int s = t - 128;
        float q = 0.f;
        #pragma unroll
        for (int i = 0; i < 48; ++i) q += a_s[i][s];
        Qs[s] = q;
    }
    __syncthreads();
    // combine + pack fp16: thread t -> channels 2t, 2t+1
    if (t < 64) {
        float4 A = Pp[0][t], B = Pp[1][t], C = Pp[2][t], D = Pp[3][t];
        __half2 h0 = __floats2half2_rn(A.x+B.x+C.x+D.x, A.y+B.y+C.y+D.y);
        __half2 h1 = __floats2half2_rn(A.z+B.z+C.z+D.z, A.w+B.w+C.w+D.w);
        uint2 u; u.x = *(unsigned*)&h0; u.y = *(unsigned*)&h1;
        ((uint2*)PqH4)[t] = u;
    }
    __syncthreads();

    // ---- Phase C: agg via fp16 SP x fp16 P (1 LDG.128 + 1 LDS.128 per iter) ----
    if (t < 128) {
        int m = t & 63, half = t >> 6;
        const uint4* SPh = d_SPh + (sel*32)*64 + m;
        float acc = 0.f;
        int cb = half*16;
        #pragma unroll 4
        for (int cq2 = cb; cq2 < cb + 16; ++cq2)
            dot8h(acc, __ldg(&SPh[cq2*64]), PqH4[cq2]);
        part[half][m] = acc;
    }
    __syncthreads();
    if (t < 64) {
        float2 bp = __ldg(&d_SPb[sel*64 + t]);
        float v = part[0][t] + part[1][t] + bp.x*Qs[0] + bp.y*Qs[1];
        ((__half*)aggH4)[t] = __float2half(v);
    }
    __syncthreads();

    // ---- Phase D: gi[gc] = Wih.agg, fp16 both sides ----
    {
        int gc = t;
        float acc = 0.f;
        #pragma unroll 4
        for (int kq2 = 0; kq2 < 8; ++kq2)
            dot8h(acc, __ldg(&d_wihh[kq2*192 + gc]), aggH4[kq2]);
        gis[gc] = acc;
    }
    __syncthreads();

    // ---- Phase E1: GRU combine (gh from smem prefetch) ----
    if (t < 64) {
        int c = t;
        float r = 1.f/(1.f+expf(-(gis[c]      + bih[c]      + ghp[c])));
        float z = 1.f/(1.f+expf(-(gis[64+c]   + bih[64+c]   + ghp[64+c])));
        float n = tanhf(gis[128+c] + bih[128+c] + r*ghp[128+c]);
        float hn = (1.f-z)*n + z*hold[c];
        float hm = maskS*hn;
        h_out[bj*64 + c] = hm;
        h_outT[c*768 + bj] = hm;
        ((__half*)hnH4)[c] = __float2half(hm);
    }
    if (!last) {
        __syncthreads();
        // ---- Phase E2: gh for NEXT layer, fp16 both sides ----
        int gc = t;
        float acc = 0.f;
        #pragma unroll 4
        for (int kq2 = 0; kq2 < 8; ++kq2)
            dot8h(acc, __ldg(&d_whhh[kq2*192 + gc]), hnH4[kq2]);
        d_gh[bj*192 + gc] = acc + bhh[gc];
    }
}

// -------- readout: 4 nodes per CTA, fp16-packed weights (unchanged) --------
__global__ void __launch_bounds__(128) readout_kernel(
   const float* __restrict__ r0b0, const float* __restrict__ r0b1,
   const float* __restrict__ r0b2, const float* __restrict__ r1b0,
   const float* __restrict__ r1b1, const float* __restrict__ r1b2) {
    __shared__ float4 xinv[128];
    __shared__ float4 bufA[128];
    __shared__ float4 bufB[128];
    int c = threadIdx.x;
    int n0 = blockIdx.x * 4;
    {
        float v[4];
        #pragma unroll
        for (int r = 0; r < 4; ++r)
            v[r] = (c < 64) ? d_hf[(n0+r)*64 + c] : d_hA[(n0+r)*64 + (c-64)];
        xinv[c] = make_float4(v[0], v[1], v[2], v[3]);
    }
    __syncthreads();

    float4 acc;
    { float b = r0b0[c]; acc = make_float4(b,b,b,b); }
    #pragma unroll 4
    for (int kq2 = 0; kq2 < 16; ++kq2)
        ro_step(acc, __ldg(&d_q0w0h[kq2*128 + c]), &xinv[8*kq2]);
    bufA[c] = make_float4(fmaxf(acc.x,0.f), fmaxf(acc.y,0.f), fmaxf(acc.z,0.f), fmaxf(acc.w,0.f));
    __syncthreads();
    { float b = r0b1[c]; acc = make_float4(b,b,b,b); }
    #pragma unroll 4
    for (int kq2 = 0; kq2 < 16; ++kq2)
        ro_step(acc, __ldg(&d_q0w1h[kq2*128 + c]), &bufA[8*kq2]);
    bufB[c] = make_float4(fmaxf(acc.x,0.f), fmaxf(acc.y,0.f), fmaxf(acc.z,0.f), fmaxf(acc.w,0.f));
    __syncthreads();
    float4 out0;
    { float b = r0b2[c]; out0 = make_float4(b,b,b,b); }
    #pragma unroll 4
    for (int kq2 = 0; kq2 < 16; ++kq2)
        ro_step(out0, __ldg(&d_q0w2h[kq2*128 + c]), &bufB[8*kq2]);
    { float b = r1b0[c]; acc = make_float4(b,b,b,b); }
    #pragma unroll 4
    for (int kq2 = 0; kq2 < 8; ++kq2)
        ro_step(acc, __ldg(&d_q1w0h[kq2*128 + c]), &xinv[64 + 8*kq2]);
    __syncthreads();
    bufA[c] = make_float4(fmaxf(acc.x,0.f), fmaxf(acc.y,0.f), fmaxf(acc.z,0.f), fmaxf(acc.w,0.f));
    __syncthreads();
    { float b = r1b1[c]; acc = make_float4(b,b,b,b); }
    #pragma unroll 4
    for (int kq2 = 0; kq2 < 16; ++kq2)
        ro_step(acc, __ldg(&d_q1w1h[kq2*128 + c]), &bufA[8*kq2]);
    __syncthreads();
    bufB[c] = make_float4(fmaxf(acc.x,0.f), fmaxf(acc.y,0.f), fmaxf(acc.z,0.f), fmaxf(acc.w,0.f));
    __syncthreads();
    float4 out1;
    { float b = r1b2[c]; out1 = make_float4(b,b,b,b); }
    #pragma unroll 4
    for (int kq2 = 0; kq2 < 16; ++kq2)
        ro_step(out1, __ldg(&d_q1w2h[kq2*128 + c]), &bufB[8*kq2]);
    d_tmp[(n0+0)*128 + c] = d_mask[n0+0]*out0.x*out1.x;
    d_tmp[(n0+1)*128 + c] = d_mask[n0+1]*out0.y*out1.y;
    d_tmp[(n0+2)*128 + c] = d_mask[n0+2]*out0.z*out1.z;
    d_tmp[(n0+3)*128 + c] = d_mask[n0+3]*out0.w*out1.w;
}

// -------- final node-sum + sigmoid --------
__global__ void reduce_kernel(float* __restrict__ out) {
    int b = blockIdx.x; int t = threadIdx.x;  // 128 threads
    float s = 0.f;
    #pragma unroll 4
    for (int j = 0; j < 48; ++j) s += d_tmp[(b*48+j)*128 + t];
    out[b*128+t] = 1.f/(1.f+expf(-s));
}

extern "C" void kernel_launch(void* const* d_in, const int* in_sizes, int n_in,
                              void* d_out, int out_size) {
    const float* g       = (const float*)d_in[0];
    const float* h0      = (const float*)d_in[1];
    const float* e       = (const float*)d_in[2];
    const float* msg_w0  = (const float*)d_in[3];
    const float* msg_b0  = (const float*)d_in[4];
    const float* msg_w1  = (const float*)d_in[5];
    const float* msg_b1  = (const float*)d_in[6];
    const float* msg_w2  = (const float*)d_in[7];
    const float* msg_b2  = (const float*)d_in[8];
    const float* gru_wih = (const float*)d_in[9];
    const float* gru_whh = (const float*)d_in[10];
    const float* gru_bih = (const float*)d_in[11];
    const float* gru_bhh = (const float*)d_in[12];
    const float* r0_w0   = (const float*)d_in[13];
    const float* r0_b0   = (const float*)d_in[14];
    const float* r0_w1   = (const float*)d_in[15];
    const float* r0_b1   = (const float*)d_in[16];
    const float* r0_w2   = (const float*)d_in[17];
    const float* r0_b2   = (const float*)d_in[18];
    const float* r1_w0   = (const float*)d_in[19];
    const float* r1_b0   = (const float*)d_in[20];
    const float* r1_w1   = (const float*)d_in[21];
    const float* r1_b1   = (const float*)d_in[22];
    const float* r1_w2   = (const float*)d_in[23];
    const float* r1_b2   = (const float*)d_in[24];
    float* out = (float*)d_out;

    cudaFuncSetAttribute(relu2_kernel, cudaFuncAttributeMaxDynamicSharedMemorySize, RELU2_SMEM);

    megaprep_kernel<<<495, 192>>>(msg_w2, msg_b2, gru_wih, gru_whh, gru_bhh,
                                  msg_w1, msg_w0, h0, g,
                                  r0_w0, r0_w1, r0_w2, r1_w0, r1_w1, r1_w2);
    relu2_kernel<<<NE/128, 256, RELU2_SMEM>>>(e, msg_b0, msg_b1);
    // L1: hf -> hA ; L2: hA -> hB ; L3: hB -> hA
    layer_kernel<<<dim3(48, 16), 192>>>(0, 1, 0, gru_bih, gru_bhh);
    layer_kernel<<<dim3(48, 16), 192>>>(1, 2, 0, gru_bih, gru_bhh);
    layer_kernel<<<dim3(48, 16), 192>>>(2, 1, 1, gru_bih, gru_bhh);
    readout_kernel<<<NNODE/4, 128>>>(r0_b0, r0_b1, r0_b2, r1_b0, r1_b1, r1_b2);
    reduce_kernel<<<NB, 128>>>(out);
}

// round 15
// speedup vs baseline: 1.0519x; 1.0519x over previous
#include <cuda_runtime.h>
#include <cuda_fp16.h>
#include <math.h>

#define NB 16
#define NN 48
#define HID 64
#define MSG 64
#define EDGE 16
#define NL 128
#define TGT 128
#define NE (NB*NN*NN)    // 36864 edges
#define NNODE (NB*NN)    // 768 nodes

// -------- device scratch (static; no allocation) --------
__device__ uint4 d_SPh[3*32*64];     // fp16 SP: [sel][cq2][m] = 8 halfs
__device__ float2 d_SPb[3*64];       // bias prefix row [sel][m] (fp32)
__device__ uint4 d_wihh[8*192];      // fp16 wih: [kq2][gc]
__device__ uint4 d_whhh[8*192];      // fp16 whh
__device__ __half d_w1t[NL*NL];      // msg_w1 transposed [n][k], fp16
__device__ __half d_w0t[NL*EDGE];    // msg_w0 transposed [n][k], fp16
__device__ __half d_r2h[NE*NL];      // relu2 fp16, TRANSPOSED: [(b*48+j)*48+i][c]
__device__ float d_gT[NNODE*NN];     // g transposed: [b*48+j][i]
__device__ float d_hf[NNODE*HID];    // h_first (normal layout)
__device__ float d_hA[NNODE*HID];
__device__ float d_hB[NNODE*HID];
__device__ float d_hfT[HID*NNODE];   // transposed: [c][node]
__device__ float d_hAT[HID*NNODE];
__device__ float d_hBT[HID*NNODE];
__device__ float d_gh[NNODE*192];    // pipelined hidden gates (incl. bhh)
__device__ float d_mask[NNODE];
__device__ float d_tmp[NNODE*TGT];
// readout weights, fp16-packed over k-octets: [kq2][c] = 8 halfs
__device__ uint4 d_q0w0h[16*128];
__device__ uint4 d_q0w1h[16*128];
__device__ uint4 d_q0w2h[16*128];
__device__ uint4 d_q1w0h[8*128];
__device__ uint4 d_q1w1h[16*128];
__device__ uint4 d_q1w2h[16*128];

#define MMA_F16(c0,c1,c2,c3,a0,a1,a2,a3,b0,b1) \
  asm volatile("mma.sync.aligned.m16n8k16.row.col.f32.f16.f16.f32 " \
    "{%0,%1,%2,%3},{%4,%5,%6,%7},{%8,%9},{%0,%1,%2,%3};" \
    : "+f"(c0),"+f"(c1),"+f"(c2),"+f"(c3) \
    : "r"(a0),"r"(a1),"r"(a2),"r"(a3),"r"(b0),"r"(b1))

// readout fp16-weight step: 8 k-values per uint4, 4 nodes wide
__device__ __forceinline__ void ro_step(float4& acc, uint4 raw, const float4* xv) {
    __half2* hp = (__half2*)&raw;
    #pragma unroll
    for (int q = 0; q < 4; ++q) {
        float2 w = __half22float2(hp[q]);
        float4 xa = xv[2*q], xb = xv[2*q+1];
        acc.x += w.x*xa.x + w.y*xb.x;
        acc.y += w.x*xa.y + w.y*xb.y;
        acc.z += w.x*xa.z + w.y*xb.z;
        acc.w += w.x*xa.w + w.y*xb.w;
    }
}

// -------- mega-prep (unchanged from R13) --------
__global__ void __launch_bounds__(192) megaprep_kernel(
        const float* __restrict__ w2, const float* __restrict__ b2,
        const float* __restrict__ wih, const float* __restrict__ whh,
        const float* __restrict__ bhh,
        const float* __restrict__ w1, const float* __restrict__ w0,
        const float* __restrict__ h0, const float* __restrict__ g,
        const float* __restrict__ r0w0, const float* __restrict__ r0w1,
        const float* __restrict__ r0w2, const float* __restrict__ r1w0,
        const float* __restrict__ r1w1, const float* __restrict__ r1w2) {
    int blk = blockIdx.x;
    int t = threadIdx.x;
    if (blk < 128) {
        if (t < 64) {
            int c = blk, m = t;
            const float* p = w2 + c*4096 + m*64;
            float acc = 0.f, s16 = 0.f, s32 = 0.f, s48 = 0.f;
            #pragma unroll
            for (int h = 0; h < 64; ++h) {
                acc += p[h];
                if (h == 15) s16 = acc;
                if (h == 31) s32 = acc;
                if (h == 47) s48 = acc;
            }
            int cq2 = c >> 2, pos = (c & 3)*2;
            __half* base = (__half*)d_SPh;
            base[(((0*32 + cq2)*64 + m))*8 + pos    ] = __float2half(s16);
            base[(((0*32 + cq2)*64 + m))*8 + pos + 1] = __float2half(acc - s16);
            base[(((1*32 + cq2)*64 + m))*8 + pos    ] = __float2half(s32);
            base[(((1*32 + cq2)*64 + m))*8 + pos + 1] = __float2half(acc - s32);
            base[(((2*32 + cq2)*64 + m))*8 + pos    ] = __float2half(s48);
            base[(((2*32 + cq2)*64 + m))*8 + pos + 1] = __float2half(acc - s48);
        }
    } else if (blk == 128) {
        if (t < 64) {
            int m = t;
            const float* q = b2 + m*64;
            float a = 0.f, t16 = 0.f, t32 = 0.f, t48 = 0.f;
            #pragma unroll
            for (int h = 0; h < 64; ++h) {
                a += q[h];
                if (h == 15) t16 = a;
                if (h == 31) t32 = a;
                if (h == 47) t48 = a;
            }
            d_SPb[0*64+m] = make_float2(t16, a - t16);
            d_SPb[1*64+m] = make_float2(t32, a - t32);
            d_SPb[2*64+m] = make_float2(t48, a - t48);
        }
    } else if (blk < 137) {
        int kq2 = blk - 129;
        __align__(16) __half hb[8];
        #pragma unroll
        for (int q = 0; q < 8; ++q) hb[q] = __float2half(wih[t*64 + 8*kq2 + q]);
        d_wihh[kq2*192 + t] = *(uint4*)hb;
    } else if (blk < 145) {
        int kq2 = blk - 137;
        __align__(16) __half hb[8];
        #pragma unroll
        for (int q = 0; q < 8; ++q) hb[q] = __float2half(whh[t*64 + 8*kq2 + q]);
        d_whhh[kq2*192 + t] = *(uint4*)hb;
    } else if (blk < 151) {
        int mat = blk - 145;
        const float* src; uint4* dst; int nkq2;
        if (mat == 0)      { src = r0w0; dst = d_q0w0h; nkq2 = 16; }
        else if (mat == 1) { src = r0w1; dst = d_q0w1h; nkq2 = 16; }
        else if (mat == 2) { src = r0w2; dst = d_q0w2h; nkq2 = 16; }
        else if (mat == 3) { src = r1w0; dst = d_q1w0h; nkq2 = 8; }
        else if (mat == 4) { src = r1w1; dst = d_q1w1h; nkq2 = 16; }
        else               { src = r1w2; dst = d_q1w2h; nkq2 = 16; }
        int total = nkq2 * 128;
        for (int idx = t; idx < total; idx += 192) {
            int kq2 = idx >> 7, c = idx & 127;
            __align__(16) __half hb[8];
            #pragma unroll
            for (int q = 0; q < 8; ++q)
                hb[q] = __float2half(src[(8*kq2+q)*128 + c]);
            dst[idx] = *(uint4*)hb;
        }
    } else if (blk < 407) {
        int nb = blk - 151;
        int node = nb*3 + t/64;
        int c = t & 63;
        __shared__ float red[192];
        float v = (c < 32) ? h0[node*32 + c] : 0.f;
        d_hf[node*64 + c] = v;
        d_hfT[c*768 + node] = v;
        red[t] = v;
        __syncthreads();
        if (c == 0) {
            float s = 0.f;
            int b0 = (t/64)*64;
            #pragma unroll
            for (int i = 0; i < 32; ++i) s += red[b0 + i];
            d_mask[node] = (s > 0.f) ? 1.f : 0.f;
        }
        int gc = t;
        float bh = bhh[gc];
        #pragma unroll
        for (int nn = 0; nn < 3; ++nn) {
            float acc = 0.f;
            #pragma unroll 4
            for (int kq = 0; kq < 16; ++kq) {
                float4 w = *(const float4*)&whh[gc*64 + 4*kq];
                acc += w.x*red[nn*64 + 4*kq]   + w.y*red[nn*64 + 4*kq+1]
                     + w.z*red[nn*64 + 4*kq+2] + w.w*red[nn*64 + 4*kq+3];
            }
            d_gh[(nb*3 + nn)*192 + gc] = acc + bh;
        }
    } else if (blk < 423) {
        int base = (blk - 407)*2304;
        for (int r = t; r < 2304; r += 192) {
            int gidx = base + r;
            int bj = gidx / 48, i = gidx % 48;
            int b = bj / 48, j = bj % 48;
            d_gT[gidx] = g[(b*48 + i)*48 + j];
        }
    } else if (blk < 487) {
        int base = (blk - 423)*256;
        for (int idx = t; idx < 256; idx += 192) {
            int i = base + idx;
            int n = i >> 7, k = i & 127;
            d_w1t[i] = __float2half(w1[k*128 + n]);
        }
    } else {
        int base = (blk - 487)*256;
        for (int idx = t; idx < 256; idx += 192) {
            int i = base + idx;
            int n = i >> 4, k = i & 15;
            d_w0t[i] = __float2half(w0[k*128 + n]);
        }
    }
}

// -------- edge MLP via fp16 tensor cores (unchanged from R13) --------
#define RELU2_SMEM ((128*136*2 + 128*16*2)*2 + 256*4)
__global__ void __launch_bounds__(256) relu2_kernel(const float* __restrict__ e,
        const float* __restrict__ b0, const float* __restrict__ b1) {
    extern __shared__ char smem_raw[];
    __half* W1H = (__half*)smem_raw;
    __half* X1H = W1H + 128*136;
    __half* ESH = X1H + 128*136;
    __half* W0H = ESH + 128*16;
    float* B0S = (float*)(W0H + 128*16);
    float* B1S = B0S + 128;
    int t = threadIdx.x;
    int row0 = blockIdx.x * 128;

    {
        const uint4* w1v = (const uint4*)d_w1t;
        for (int idx = t; idx < 2048; idx += 256) {
            int n = idx >> 4, kq = idx & 15;
            *(uint4*)&W1H[n*136 + kq*8] = __ldg(&w1v[idx]);
        }
        const float4* ev = (const float4*)(e + row0*16);
        for (int idx = t; idx < 512; idx += 256) {
            float4 x = __ldg(&ev[idx]);
            int r = idx >> 2, kq = idx & 3;
            uint2 u;
            __half2 h0 = __floats2half2_rn(x.x, x.y);
            __half2 h1 = __floats2half2_rn(x.z, x.w);
            u.x = *(unsigned*)&h0; u.y = *(unsigned*)&h1;
            *(uint2*)&ESH[r*16 + kq*4] = u;
        }
        const uint4* w0v = (const uint4*)d_w0t;
        if (t < 256) {
            int n = t >> 1, hq = t & 1;
            *(uint4*)&W0H[n*16 + hq*8] = __ldg(&w0v[t]);
        }
        if (t < 128) { B0S[t] = b0[t]; B1S[t] = b1[t]; }
    }
    __syncthreads();

    int lane = t & 31, warp = t >> 5;
    int rbase = warp * 16;
    int grp = lane >> 2, tig = lane & 3;

    float acc[16][4];
    #pragma unroll
    for (int nt = 0; nt < 16; ++nt) {
        float bv0 = B0S[nt*8 + 2*tig], bv1 = B0S[nt*8 + 2*tig + 1];
        acc[nt][0] = bv0; acc[nt][1] = bv1; acc[nt][2] = bv0; acc[nt][3] = bv1;
    }
    {
        unsigned a0 = *(unsigned*)&ESH[(rbase+grp  )*16 + 2*tig];
        unsigned a1 = *(unsigned*)&ESH[(rbase+grp+8)*16 + 2*tig];
        unsigned a2 = *(unsigned*)&ESH[(rbase+grp  )*16 + 8 + 2*tig];
        unsigned a3 = *(unsigned*)&ESH[(rbase+grp+8)*16 + 8 + 2*tig];
        #pragma unroll
        for (int nt = 0; nt < 16; ++nt) {
            unsigned bb0 = *(unsigned*)&W0H[(nt*8+grp)*16 + 2*tig];
            unsigned bb1 = *(unsigned*)&W0H[(nt*8+grp)*16 + 8 + 2*tig];
            MMA_F16(acc[nt][0],acc[nt][1],acc[nt][2],acc[nt][3],a0,a1,a2,a3,bb0,bb1);
        }
    }
    #pragma unroll
    for (int nt = 0; nt < 16; ++nt) {
        __half2 lo = __floats2half2_rn(fmaxf(acc[nt][0],0.f), fmaxf(acc[nt][1],0.f));
        __half2 hi = __floats2half2_rn(fmaxf(acc[nt][2],0.f), fmaxf(acc[nt][3],0.f));
        *(__half2*)&X1H[(rbase+grp  )*136 + nt*8 + 2*tig] = lo;
        *(__half2*)&X1H[(rbase+grp+8)*136 + nt*8 + 2*tig] = hi;
    }
    __syncthreads();

    #pragma unroll
    for (int nt = 0; nt < 16; ++nt) {
        float bv0 = B1S[nt*8 + 2*tig], bv1 = B1S[nt*8 + 2*tig + 1];
        acc[nt][0] = bv0; acc[nt][1] = bv1; acc[nt][2] = bv0; acc[nt][3] = bv1;
    }
    #pragma unroll
    for (int kt = 0; kt < 8; ++kt) {
        unsigned a0 = *(unsigned*)&X1H[(rbase+grp  )*136 + kt*16 + 2*tig];
        unsigned a1 = *(unsigned*)&X1H[(rbase+grp+8)*136 + kt*16 + 2*tig];
        unsigned a2 = *(unsigned*)&X1H[(rbase+grp  )*136 + kt*16 + 8 + 2*tig];
        unsigned a3 = *(unsigned*)&X1H[(rbase+grp+8)*136 + kt*16 + 8 + 2*tig];
        #pragma unroll
        for (int nt = 0; nt < 16; ++nt) {
            unsigned bb0 = *(unsigned*)&W1H[(nt*8+grp)*136 + kt*16 + 2*tig];
            unsigned bb1 = *(unsigned*)&W1H[(nt*8+grp)*136 + kt*16 + 8 + 2*tig];
            MMA_F16(acc[nt][0],acc[nt][1],acc[nt][2],acc[nt][3],a0,a1,a2,a3,bb0,bb1);
        }
    }
    __syncthreads();

    __half2* H = (__half2*)X1H;
    #pragma unroll
    for (int nt = 0; nt < 16; ++nt) {
        H[(rbase+grp  )*68 + nt*4 + tig] =
            __floats2half2_rn(fmaxf(acc[nt][0],0.f), fmaxf(acc[nt][1],0.f));
        H[(rbase+grp+8)*68 + nt*4 + tig] =
            __floats2half2_rn(fmaxf(acc[nt][2],0.f), fmaxf(acc[nt][3],0.f));
    }
    __syncthreads();
    for (int idx = t; idx < 2048; idx += 256) {
        int r = idx >> 4, chunk = idx & 15;
        int row = row0 + r;
        int b = row / 2304; int rem = row - b*2304;
        int i = rem / 48;   int j = rem - i*48;
        uint4 v = *(const uint4*)((const char*)X1H + (size_t)r*272 + chunk*16);
        *(uint4*)(d_r2h + (size_t)((b*48 + j)*48 + i)*128 + chunk*8) = v;
    }
}

// -------- fused layer: R13 code + gh/mask smem prefetch --------
__global__ void __launch_bounds__(192) layer_kernel(int inbuf, int outbuf, int last,
        const float* __restrict__ bih, const float* __restrict__ bhh) {
    const float* h_in   = (inbuf  == 0) ? d_hf  : ((inbuf  == 1) ? d_hA  : d_hB);
    const float* h_inT  = (inbuf  == 0) ? d_hfT : ((inbuf  == 1) ? d_hAT : d_hBT);
    float*       h_out  = (outbuf == 1) ? d_hA  : d_hB;
    float*       h_outT = (outbuf == 1) ? d_hAT : d_hBT;
    int j = blockIdx.x; int b = blockIdx.y;
    int t = threadIdx.x;
    int bj = b*48 + j;
    int k0 = (4*j)/3;
    int a64 = (16*j) % 48;
    int sel = (48 - a64)/16 - 1;

    __shared__ float a_s[48][2];
    __shared__ float hold[64];
    __shared__ float4 Pp[4][64];
    __shared__ float4 Pq[64];
    __shared__ float part[2][64];
    __shared__ float4 aggq[16];
    __shared__ float gis[192];
    __shared__ float4 hnq[16];
    __shared__ float ghp[192];
    __shared__ float Qs[2];
    __shared__ float maskS;

    // ---- Phase A (+ gh/mask prefetch) ----
    ghp[t] = __ldg(&d_gh[bj*192 + t]);
    if (t < 96) {
        int s = t / 48, i = t % 48;
        float hv = __ldg(&h_inT[(k0+s)*768 + b*48 + i]);
        float gv = __ldg(&d_gT[bj*48 + i]);
        a_s[i][s] = gv * hv;
    } else if (t < 160) {
        int c = t - 96;
        hold[c] = h_in[bj*64 + c];
    } else if (t == 160) {
        maskS = d_mask[bj];
    }
    __syncthreads();

    if (t < 128) {
        int tq = t & 31, ig = t >> 5;
        const uint2* r2p = (const uint2*)(d_r2h + (size_t)bj*6144) + tq;
        float p00=0.f,p01=0.f,p02=0.f,p03=0.f;
        float p10=0.f,p11=0.f,p12=0.f,p13=0.f;
        int ibeg = ig*12;
        #pragma unroll
        for (int i = ibeg; i < ibeg + 12; ++i) {
            uint2 raw = __ldg(&r2p[i*32]);
            float2 v0 = __half22float2(*(__half2*)&raw.x);
            float2 v1 = __half22float2(*(__half2*)&raw.y);
            float2 aa = *(float2*)&a_s[i][0];
            p00 += aa.x*v0.x; p01 += aa.x*v0.y; p02 += aa.x*v1.x; p03 += aa.x*v1.y;
            p10 += aa.y*v0.x; p11 += aa.y*v0.y; p12 += aa.y*v1.x; p13 += aa.y*v1.y;
        }
        Pp[ig][2*tq]   = make_float4(p00, p10, p01, p11);
        Pp[ig][2*tq+1] = make_float4(p02, p12, p03, p13);
    } else if (t < 130) {
        int s = t - 128;
        float q = 0.f;
        #pragma unroll
        for (int i = 0; i < 48; ++i) q += a_s[i][s];
        Qs[s] = q;
    }
    __syncthreads();
    if (t < 64) {
        float4 A = Pp[0][t], B = Pp[1][t], C = Pp[2][t], D = Pp[3][t];
        Pq[t] = make_float4(A.x+B.x+C.x+D.x, A.y+B.y+C.y+D.y,
                            A.z+B.z+C.z+D.z, A.w+B.w+C.w+D.w);
    }
    __syncthreads();

    if (t < 128) {
        int m = t & 63, half = t >> 6;
        const uint4* SPh = d_SPh + (sel*32)*64 + m;
        float acc = 0.f;
        int cb = half*16;
        #pragma unroll 4
        for (int cq2 = cb; cq2 < cb + 16; ++cq2) {
            uint4 raw = __ldg(&SPh[cq2*64]);
            __half2* hp = (__half2*)&raw;
            float2 s0 = __half22float2(hp[0]);
            float2 s1 = __half22float2(hp[1]);
            float2 s2 = __half22float2(hp[2]);
            float2 s3 = __half22float2(hp[3]);
            float4 pA = Pq[2*cq2], pB = Pq[2*cq2+1];
            acc += s0.x*pA.x + s0.y*pA.y + s1.x*pA.z + s1.y*pA.w
                 + s2.x*pB.x + s2.y*pB.y + s3.x*pB.z + s3.y*pB.w;
        }
        part[half][m] = acc;
    }
    __syncthreads();
    if (t < 64) {
        float2 bp = __ldg(&d_SPb[sel*64 + t]);
        ((float*)aggq)[t] = part[0][t] + part[1][t] + bp.x*Qs[0] + bp.y*Qs[1];
    }
    __syncthreads();

    {
        int gc = t;
        float acc = 0.f;
        #pragma unroll 4
        for (int kq2 = 0; kq2 < 8; ++kq2) {
            uint4 raw = __ldg(&d_wihh[kq2*192 + gc]);
            __half2* hp = (__half2*)&raw;
            float2 w0 = __half22float2(hp[0]);
            float2 w1 = __half22float2(hp[1]);
            float2 w2 = __half22float2(hp[2]);
            float2 w3 = __half22float2(hp[3]);
            float4 a0 = aggq[2*kq2], a1 = aggq[2*kq2+1];
            acc += w0.x*a0.x + w0.y*a0.y + w1.x*a0.z + w1.y*a0.w
                 + w2.x*a1.x + w2.y*a1.y + w3.x*a1.z + w3.y*a1.w;
        }
        gis[gc] = acc;
    }
    __syncthreads();

    if (t < 64) {
        int c = t;
        float r = 1.f/(1.f+expf(-(gis[c]      + bih[c]      + ghp[c])));
        float z = 1.f/(1.f+expf(-(gis[64+c]   + bih[64+c]   + ghp[64+c])));
        float n = tanhf(gis[128+c] + bih[128+c] + r*ghp[128+c]);
        float hn = (1.f-z)*n + z*hold[c];
        float hm = maskS*hn;
        h_out[bj*64 + c] = hm;
        h_outT[c*768 + bj] = hm;
        ((float*)hnq)[c] = hm;
    }
    if (!last) {
        __syncthreads();
        int gc = t;
        float acc = 0.f;
        #pragma unroll 4
        for (int kq2 = 0; kq2 < 8; ++kq2) {
            uint4 raw = __ldg(&d_whhh[kq2*192 + gc]);
            __half2* hp = (__half2*)&raw;
            float2 w0 = __half22float2(hp[0]);
            float2 w1 = __half22float2(hp[1]);
            float2 w2 = __half22float2(hp[2]);
            float2 w3 = __half22float2(hp[3]);
            float4 h0q = hnq[2*kq2], h1q = hnq[2*kq2+1];
            acc += w0.x*h0q.x + w0.y*h0q.y + w1.x*h0q.z + w1.y*h0q.w
                 + w2.x*h1q.x + w2.y*h1q.y + w3.x*h1q.z + w3.y*h1q.w;
        }
        d_gh[bj*192 + gc] = acc + bhh[gc];
    }
}

// -------- readout: 4 nodes per CTA, fp16-packed weights (unchanged) --------
__global__ void __launch_bounds__(128) readout_kernel(
   const float* __restrict__ r0b0, const float* __restrict__ r0b1,
   const float* __restrict__ r0b2, const float* __restrict__ r1b0,
   const float* __restrict__ r1b1, const float* __restrict__ r1b2) {
    __shared__ float4 xinv[128];
    __shared__ float4 bufA[128];
    __shared__ float4 bufB[128];
    int c = threadIdx.x;
    int n0 = blockIdx.x * 4;
    {
        float v[4];
        #pragma unroll
        for (int r = 0; r < 4; ++r)
            v[r] = (c < 64) ? d_hf[(n0+r)*64 + c] : d_hA[(n0+r)*64 + (c-64)];
        xinv[c] = make_float4(v[0], v[1], v[2], v[3]);
    }
    __syncthreads();

    float4 acc;
    { float b = r0b0[c]; acc = make_float4(b,b,b,b); }
    #pragma unroll 4
    for (int kq2 = 0; kq2 < 16; ++kq2)
        ro_step(acc, __ldg(&d_q0w0h[kq2*128 + c]), &xinv[8*kq2]);
    bufA[c] = make_float4(fmaxf(acc.x,0.f), fmaxf(acc.y,0.f), fmaxf(acc.z,0.f), fmaxf(acc.w,0.f));
    __syncthreads();
    { float b = r0b1[c]; acc = make_float4(b,b,b,b); }
    #pragma unroll 4
    for (int kq2 = 0; kq2 < 16; ++kq2)
        ro_step(acc, __ldg(&d_q0w1h[kq2*128 + c]), &bufA[8*kq2]);
    bufB[c] = make_float4(fmaxf(acc.x,0.f), fmaxf(acc.y,0.f), fmaxf(acc.z,0.f), fmaxf(acc.w,0.f));
    __syncthreads();
    float4 out0;
    { float b = r0b2[c]; out0 = make_float4(b,b,b,b); }
    #pragma unroll 4
    for (int kq2 = 0; kq2 < 16; ++kq2)
        ro_step(out0, __ldg(&d_q0w2h[kq2*128 + c]), &bufB[8*kq2]);
    { float b = r1b0[c]; acc = make_float4(b,b,b,b); }
    #pragma unroll 4
    for (int kq2 = 0; kq2 < 8; ++kq2)
        ro_step(acc, __ldg(&d_q1w0h[kq2*128 + c]), &xinv[64 + 8*kq2]);
    __syncthreads();
    bufA[c] = make_float4(fmaxf(acc.x,0.f), fmaxf(acc.y,0.f), fmaxf(acc.z,0.f), fmaxf(acc.w,0.f));
    __syncthreads();
    { float b = r1b1[c]; acc = make_float4(b,b,b,b); }
    #pragma unroll 4
    for (int kq2 = 0; kq2 < 16; ++kq2)
        ro_step(acc, __ldg(&d_q1w1h[kq2*128 + c]), &bufA[8*kq2]);
    __syncthreads();
    bufB[c] = make_float4(fmaxf(acc.x,0.f), fmaxf(acc.y,0.f), fmaxf(acc.z,0.f), fmaxf(acc.w,0.f));
    __syncthreads();
    float4 out1;
    { float b = r1b2[c]; out1 = make_float4(b,b,b,b); }
    #pragma unroll 4
    for (int kq2 = 0; kq2 < 16; ++kq2)
        ro_step(out1, __ldg(&d_q1w2h[kq2*128 + c]), &bufB[8*kq2]);
    d_tmp[(n0+0)*128 + c] = d_mask[n0+0]*out0.x*out1.x;
    d_tmp[(n0+1)*128 + c] = d_mask[n0+1]*out0.y*out1.y;
    d_tmp[(n0+2)*128 + c] = d_mask[n0+2]*out0.z*out1.z;
    d_tmp[(n0+3)*128 + c] = d_mask[n0+3]*out0.w*out1.w;
}

// -------- final node-sum + sigmoid --------
__global__ void reduce_kernel(float* __restrict__ out) {
    int b = blockIdx.x; int t = threadIdx.x;  // 128 threads
    float s = 0.f;
    #pragma unroll 4
    for (int j = 0; j < 48; ++j) s += d_tmp[(b*48+j)*128 + t];
    out[b*128+t] = 1.f/(1.f+expf(-s));
}

extern "C" void kernel_launch(void* const* d_in, const int* in_sizes, int n_in,
                              void* d_out, int out_size) {
    const float* g       = (const float*)d_in[0];
    const float* h0      = (const float*)d_in[1];
    const float* e       = (const float*)d_in[2];
    const float* msg_w0  = (const float*)d_in[3];
    const float* msg_b0  = (const float*)d_in[4];
    const float* msg_w1  = (const float*)d_in[5];
    const float* msg_b1  = (const float*)d_in[6];
    const float* msg_w2  = (const float*)d_in[7];
    const float* msg_b2  = (const float*)d_in[8];
    const float* gru_wih = (const float*)d_in[9];
    const float* gru_whh = (const float*)d_in[10];
    const float* gru_bih = (const float*)d_in[11];
    const float* gru_bhh = (const float*)d_in[12];
    const float* r0_w0   = (const float*)d_in[13];
    const float* r0_b0   = (const float*)d_in[14];
    const float* r0_w1   = (const float*)d_in[15];
    const float* r0_b1   = (const float*)d_in[16];
    const float* r0_w2   = (const float*)d_in[17];
    const float* r0_b2   = (const float*)d_in[18];
    const float* r1_w0   = (const float*)d_in[19];
    const float* r1_b0   = (const float*)d_in[20];
    const float* r1_w1   = (const float*)d_in[21];
    const float* r1_b1   = (const float*)d_in[22];
    const float* r1_w2   = (const float*)d_in[23];
    const float* r1_b2   = (const float*)d_in[24];
    float* out = (float*)d_out;

    cudaFuncSetAttribute(relu2_kernel, cudaFuncAttributeMaxDynamicSharedMemorySize, RELU2_SMEM);

    megaprep_kernel<<<495, 192>>>(msg_w2, msg_b2, gru_wih, gru_whh, gru_bhh,
                                  msg_w1, msg_w0, h0, g,
                                  r0_w0, r0_w1, r0_w2, r1_w0, r1_w1, r1_w2);
    relu2_kernel<<<NE/128, 256, RELU2_SMEM>>>(e, msg_b0, msg_b1);
    // L1: hf -> hA ; L2: hA -> hB ; L3: hB -> hA
    layer_kernel<<<dim3(48, 16), 192>>>(0, 1, 0, gru_bih, gru_bhh);
    layer_kernel<<<dim3(48, 16), 192>>>(1, 2, 0, gru_bih, gru_bhh);
    layer_kernel<<<dim3(48, 16), 192>>>(2, 1, 1, gru_bih, gru_bhh);
    readout_kernel<<<NNODE/4, 128>>>(r0_b0, r0_b1, r0_b2, r1_b0, r1_b1, r1_b2);
    reduce_kernel<<<NB, 128>>>(out);
}

// round 16
// speedup vs baseline: 1.0571x; 1.0050x over previous
#include <cuda_runtime.h>
#include <cuda_fp16.h>
#include <math.h>

#define NB 16
#define NN 48
#define HID 64
#define MSG 64
#define EDGE 16
#define NL 128
#define TGT 128
#define NE (NB*NN*NN)    // 36864 edges
#define NNODE (NB*NN)    // 768 nodes

// -------- device scratch (static; no allocation) --------
__device__ uint4 d_SPh[3*32*64];     // fp16 SP: [sel][cq2][m] = 8 halfs
__device__ float2 d_SPb[3*64];       // bias prefix row [sel][m] (fp32)
__device__ uint4 d_wihh[8*192];      // fp16 wih: [kq2][gc]
__device__ uint4 d_whhh[8*192];      // fp16 whh
__device__ __half d_w1t[NL*NL];      // msg_w1 transposed [n][k], fp16
__device__ __half d_w0t[NL*EDGE];    // msg_w0 transposed [n][k], fp16
__device__ __half d_r2h[NE*NL];      // relu2 fp16, TRANSPOSED: [(b*48+j)*48+i][c]
__device__ float d_gT[NNODE*NN];     // g transposed: [b*48+j][i]
__device__ float d_hf[NNODE*HID];    // h_first (normal layout)
__device__ float d_hA[NNODE*HID];
__device__ float d_hB[NNODE*HID];
__device__ float d_hfT[HID*NNODE];   // transposed: [c][node]
__device__ float d_hAT[HID*NNODE];
__device__ float d_hBT[HID*NNODE];
__device__ float d_gh[NNODE*192];    // pipelined hidden gates (incl. bhh)
__device__ float d_mask[NNODE];
__device__ float d_tmp[NNODE*TGT];
__device__ unsigned d_cnt[NB];       // readout completion tickets per batch
// readout weights, fp16-packed over k-octets: [kq2][c] = 8 halfs
__device__ uint4 d_q0w0h[16*128];
__device__ uint4 d_q0w1h[16*128];
__device__ uint4 d_q0w2h[16*128];
__device__ uint4 d_q1w0h[8*128];
__device__ uint4 d_q1w1h[16*128];
__device__ uint4 d_q1w2h[16*128];

#define MMA_F16(c0,c1,c2,c3,a0,a1,a2,a3,b0,b1) \
  asm volatile("mma.sync.aligned.m16n8k16.row.col.f32.f16.f16.f32 " \
    "{%0,%1,%2,%3},{%4,%5,%6,%7},{%8,%9},{%0,%1,%2,%3};" \
    : "+f"(c0),"+f"(c1),"+f"(c2),"+f"(c3) \
    : "r"(a0),"r"(a1),"r"(a2),"r"(a3),"r"(b0),"r"(b1))

// readout fp16-weight step: 8 k-values per uint4, 4 nodes wide
__device__ __forceinline__ void ro_step(float4& acc, uint4 raw, const float4* xv) {
    __half2* hp = (__half2*)&raw;
    #pragma unroll
    for (int q = 0; q < 4; ++q) {
        float2 w = __half22float2(hp[q]);
        float4 xa = xv[2*q], xb = xv[2*q+1];
        acc.x += w.x*xa.x + w.y*xb.x;
        acc.y += w.x*xa.y + w.y*xb.y;
        acc.z += w.x*xa.z + w.y*xb.z;
        acc.w += w.x*xa.w + w.y*xb.w;
    }
}

// -------- mega-prep (R13 + d_cnt zeroing) --------
__global__ void __launch_bounds__(192) megaprep_kernel(
        const float* __restrict__ w2, const float* __restrict__ b2,
        const float* __restrict__ wih, const float* __restrict__ whh,
        const float* __restrict__ bhh,
        const float* __restrict__ w1, const float* __restrict__ w0,
        const float* __restrict__ h0, const float* __restrict__ g,
        const float* __restrict__ r0w0, const float* __restrict__ r0w1,
        const float* __restrict__ r0w2, const float* __restrict__ r1w0,
        const float* __restrict__ r1w1, const float* __restrict__ r1w2) {
    int blk = blockIdx.x;
    int t = threadIdx.x;
    if (blk < 128) {
        if (t < 64) {
            int c = blk, m = t;
            const float* p = w2 + c*4096 + m*64;
            float acc = 0.f, s16 = 0.f, s32 = 0.f, s48 = 0.f;
            #pragma unroll
            for (int h = 0; h < 64; ++h) {
                acc += p[h];
                if (h == 15) s16 = acc;
                if (h == 31) s32 = acc;
                if (h == 47) s48 = acc;
            }
            int cq2 = c >> 2, pos = (c & 3)*2;
            __half* base = (__half*)d_SPh;
            base[(((0*32 + cq2)*64 + m))*8 + pos    ] = __float2half(s16);
            base[(((0*32 + cq2)*64 + m))*8 + pos + 1] = __float2half(acc - s16);
            base[(((1*32 + cq2)*64 + m))*8 + pos    ] = __float2half(s32);
            base[(((1*32 + cq2)*64 + m))*8 + pos + 1] = __float2half(acc - s32);
            base[(((2*32 + cq2)*64 + m))*8 + pos    ] = __float2half(s48);
            base[(((2*32 + cq2)*64 + m))*8 + pos + 1] = __float2half(acc - s48);
        }
    } else if (blk == 128) {
        if (t < 64) {
            int m = t;
            const float* q = b2 + m*64;
            float a = 0.f, t16 = 0.f, t32 = 0.f, t48 = 0.f;
            #pragma unroll
            for (int h = 0; h < 64; ++h) {
                a += q[h];
                if (h == 15) t16 = a;
                if (h == 31) t32 = a;
                if (h == 47) t48 = a;
            }
            d_SPb[0*64+m] = make_float2(t16, a - t16);
            d_SPb[1*64+m] = make_float2(t32, a - t32);
            d_SPb[2*64+m] = make_float2(t48, a - t48);
        }
        if (t >= 64 && t < 80) d_cnt[t - 64] = 0u;
    } else if (blk < 137) {
        int kq2 = blk - 129;
        __align__(16) __half hb[8];
        #pragma unroll
        for (int q = 0; q < 8; ++q) hb[q] = __float2half(wih[t*64 + 8*kq2 + q]);
        d_wihh[kq2*192 + t] = *(uint4*)hb;
    } else if (blk < 145) {
        int kq2 = blk - 137;
        __align__(16) __half hb[8];
        #pragma unroll
        for (int q = 0; q < 8; ++q) hb[q] = __float2half(whh[t*64 + 8*kq2 + q]);
        d_whhh[kq2*192 + t] = *(uint4*)hb;
    } else if (blk < 151) {
        int mat = blk - 145;
        const float* src; uint4* dst; int nkq2;
        if (mat == 0)      { src = r0w0; dst = d_q0w0h; nkq2 = 16; }
        else if (mat == 1) { src = r0w1; dst = d_q0w1h; nkq2 = 16; }
        else if (mat == 2) { src = r0w2; dst = d_q0w2h; nkq2 = 16; }
        else if (mat == 3) { src = r1w0; dst = d_q1w0h; nkq2 = 8; }
        else if (mat == 4) { src = r1w1; dst = d_q1w1h; nkq2 = 16; }
        else               { src = r1w2; dst = d_q1w2h; nkq2 = 16; }
        int total = nkq2 * 128;
        for (int idx = t; idx < total; idx += 192) {
            int kq2 = idx >> 7, c = idx & 127;
            __align__(16) __half hb[8];
            #pragma unroll
            for (int q = 0; q < 8; ++q)
                hb[q] = __float2half(src[(8*kq2+q)*128 + c]);
            dst[idx] = *(uint4*)hb;
        }
    } else if (blk < 407) {
        int nb = blk - 151;
        int node = nb*3 + t/64;
        int c = t & 63;
        __shared__ float red[192];
        float v = (c < 32) ? h0[node*32 + c] : 0.f;
        d_hf[node*64 + c] = v;
        d_hfT[c*768 + node] = v;
        red[t] = v;
        __syncthreads();
        if (c == 0) {
            float s = 0.f;
            int b0 = (t/64)*64;
            #pragma unroll
            for (int i = 0; i < 32; ++i) s += red[b0 + i];
            d_mask[node] = (s > 0.f) ? 1.f : 0.f;
        }
        int gc = t;
        float bh = bhh[gc];
        #pragma unroll
        for (int nn = 0; nn < 3; ++nn) {
            float acc = 0.f;
            #pragma unroll 4
            for (int kq = 0; kq < 16; ++kq) {
                float4 w = *(const float4*)&whh[gc*64 + 4*kq];
                acc += w.x*red[nn*64 + 4*kq]   + w.y*red[nn*64 + 4*kq+1]
                     + w.z*red[nn*64 + 4*kq+2] + w.w*red[nn*64 + 4*kq+3];
            }
            d_gh[(nb*3 + nn)*192 + gc] = acc + bh;
        }
    } else if (blk < 423) {
        int base = (blk - 407)*2304;
        for (int r = t; r < 2304; r += 192) {
            int gidx = base + r;
            int bj = gidx / 48, i = gidx % 48;
            int b = bj / 48, j = bj % 48;
            d_gT[gidx] = g[(b*48 + i)*48 + j];
        }
    } else if (blk < 487) {
        int base = (blk - 423)*256;
        for (int idx = t; idx < 256; idx += 192) {
            int i = base + idx;
            int n = i >> 7, k = i & 127;
            d_w1t[i] = __float2half(w1[k*128 + n]);
        }
    } else {
        int base = (blk - 487)*256;
        for (int idx = t; idx < 256; idx += 192) {
            int i = base + idx;
            int n = i >> 4, k = i & 15;
            d_w0t[i] = __float2half(w0[k*128 + n]);
        }
    }
}

// -------- edge MLP via fp16 tensor cores (unchanged from R13) --------
#define RELU2_SMEM ((128*136*2 + 128*16*2)*2 + 256*4)
__global__ void __launch_bounds__(256) relu2_kernel(const float* __restrict__ e,
        const float* __restrict__ b0, const float* __restrict__ b1) {
    extern __shared__ char smem_raw[];
    __half* W1H = (__half*)smem_raw;
    __half* X1H = W1H + 128*136;
    __half* ESH = X1H + 128*136;
    __half* W0H = ESH + 128*16;
    float* B0S = (float*)(W0H + 128*16);
    float* B1S = B0S + 128;
    int t = threadIdx.x;
    int row0 = blockIdx.x * 128;

    {
        const uint4* w1v = (const uint4*)d_w1t;
        for (int idx = t; idx < 2048; idx += 256) {
            int n = idx >> 4, kq = idx & 15;
            *(uint4*)&W1H[n*136 + kq*8] = __ldg(&w1v[idx]);
        }
        const float4* ev = (const float4*)(e + row0*16);
        for (int idx = t; idx < 512; idx += 256) {
            float4 x = __ldg(&ev[idx]);
            int r = idx >> 2, kq = idx & 3;
            uint2 u;
            __half2 h0 = __floats2half2_rn(x.x, x.y);
            __half2 h1 = __floats2half2_rn(x.z, x.w);
            u.x = *(unsigned*)&h0; u.y = *(unsigned*)&h1;
            *(uint2*)&ESH[r*16 + kq*4] = u;
        }
        const uint4* w0v = (const uint4*)d_w0t;
        if (t < 256) {
            int n = t >> 1, hq = t & 1;
            *(uint4*)&W0H[n*16 + hq*8] = __ldg(&w0v[t]);
        }
        if (t < 128) { B0S[t] = b0[t]; B1S[t] = b1[t]; }
    }
    __syncthreads();

    int lane = t & 31, warp = t >> 5;
    int rbase = warp * 16;
    int grp = lane >> 2, tig = lane & 3;

    float acc[16][4];
    #pragma unroll
    for (int nt = 0; nt < 16; ++nt) {
        float bv0 = B0S[nt*8 + 2*tig], bv1 = B0S[nt*8 + 2*tig + 1];
        acc[nt][0] = bv0; acc[nt][1] = bv1; acc[nt][2] = bv0; acc[nt][3] = bv1;
    }
    {
        unsigned a0 = *(unsigned*)&ESH[(rbase+grp  )*16 + 2*tig];
        unsigned a1 = *(unsigned*)&ESH[(rbase+grp+8)*16 + 2*tig];
        unsigned a2 = *(unsigned*)&ESH[(rbase+grp  )*16 + 8 + 2*tig];
        unsigned a3 = *(unsigned*)&ESH[(rbase+grp+8)*16 + 8 + 2*tig];
        #pragma unroll
        for (int nt = 0; nt < 16; ++nt) {
            unsigned bb0 = *(unsigned*)&W0H[(nt*8+grp)*16 + 2*tig];
            unsigned bb1 = *(unsigned*)&W0H[(nt*8+grp)*16 + 8 + 2*tig];
            MMA_F16(acc[nt][0],acc[nt][1],acc[nt][2],acc[nt][3],a0,a1,a2,a3,bb0,bb1);
        }
    }
    #pragma unroll
    for (int nt = 0; nt < 16; ++nt) {
        __half2 lo = __floats2half2_rn(fmaxf(acc[nt][0],0.f), fmaxf(acc[nt][1],0.f));
        __half2 hi = __floats2half2_rn(fmaxf(acc[nt][2],0.f), fmaxf(acc[nt][3],0.f));
        *(__half2*)&X1H[(rbase+grp  )*136 + nt*8 + 2*tig] = lo;
        *(__half2*)&X1H[(rbase+grp+8)*136 + nt*8 + 2*tig] = hi;
    }
    __syncthreads();

    #pragma unroll
    for (int nt = 0; nt < 16; ++nt) {
        float bv0 = B1S[nt*8 + 2*tig], bv1 = B1S[nt*8 + 2*tig + 1];
        acc[nt][0] = bv0; acc[nt][1] = bv1; acc[nt][2] = bv0; acc[nt][3] = bv1;
    }
    #pragma unroll
    for (int kt = 0; kt < 8; ++kt) {
        unsigned a0 = *(unsigned*)&X1H[(rbase+grp  )*136 + kt*16 + 2*tig];
        unsigned a1 = *(unsigned*)&X1H[(rbase+grp+8)*136 + kt*16 + 2*tig];
        unsigned a2 = *(unsigned*)&X1H[(rbase+grp  )*136 + kt*16 + 8 + 2*tig];
        unsigned a3 = *(unsigned*)&X1H[(rbase+grp+8)*136 + kt*16 + 8 + 2*tig];
        #pragma unroll
        for (int nt = 0; nt < 16; ++nt) {
            unsigned bb0 = *(unsigned*)&W1H[(nt*8+grp)*136 + kt*16 + 2*tig];
            unsigned bb1 = *(unsigned*)&W1H[(nt*8+grp)*136 + kt*16 + 8 + 2*tig];
            MMA_F16(acc[nt][0],acc[nt][1],acc[nt][2],acc[nt][3],a0,a1,a2,a3,bb0,bb1);
        }
    }
    __syncthreads();

    __half2* H = (__half2*)X1H;
    #pragma unroll
    for (int nt = 0; nt < 16; ++nt) {
        H[(rbase+grp  )*68 + nt*4 + tig] =
            __floats2half2_rn(fmaxf(acc[nt][0],0.f), fmaxf(acc[nt][1],0.f));
        H[(rbase+grp+8)*68 + nt*4 + tig] =
            __floats2half2_rn(fmaxf(acc[nt][2],0.f), fmaxf(acc[nt][3],0.f));
    }
    __syncthreads();
    for (int idx = t; idx < 2048; idx += 256) {
        int r = idx >> 4, chunk = idx & 15;
        int row = row0 + r;
        int b = row / 2304; int rem = row - b*2304;
        int i = rem / 48;   int j = rem - i*48;
        uint4 v = *(const uint4*)((const char*)X1H + (size_t)r*272 + chunk*16);
        *(uint4*)(d_r2h + (size_t)((b*48 + j)*48 + i)*128 + chunk*8) = v;
    }
}

// -------- fused layer: EXACT R13 code --------
__global__ void __launch_bounds__(192) layer_kernel(int inbuf, int outbuf, int last,
        const float* __restrict__ bih, const float* __restrict__ bhh) {
    const float* h_in   = (inbuf  == 0) ? d_hf  : ((inbuf  == 1) ? d_hA  : d_hB);
    const float* h_inT  = (inbuf  == 0) ? d_hfT : ((inbuf  == 1) ? d_hAT : d_hBT);
    float*       h_out  = (outbuf == 1) ? d_hA  : d_hB;
    float*       h_outT = (outbuf == 1) ? d_hAT : d_hBT;
    int j = blockIdx.x; int b = blockIdx.y;
    int t = threadIdx.x;
    int bj = b*48 + j;
    int k0 = (4*j)/3;
    int a64 = (16*j) % 48;
    int sel = (48 - a64)/16 - 1;

    __shared__ float a_s[48][2];
    __shared__ float hold[64];
    __shared__ float4 Pp[4][64];
    __shared__ float4 Pq[64];
    __shared__ float part[2][64];
    __shared__ float4 aggq[16];
    __shared__ float gis[192];
    __shared__ float4 hnq[16];
    __shared__ float Qs[2];

    if (t < 96) {
        int s = t / 48, i = t % 48;
        float hv = __ldg(&h_inT[(k0+s)*768 + b*48 + i]);
        float gv = __ldg(&d_gT[bj*48 + i]);
        a_s[i][s] = gv * hv;
    } else if (t < 160) {
        int c = t - 96;
        hold[c] = h_in[bj*64 + c];
    }
    __syncthreads();

    if (t < 128) {
        int tq = t & 31, ig = t >> 5;
        const uint2* r2p = (const uint2*)(d_r2h + (size_t)bj*6144) + tq;
        float p00=0.f,p01=0.f,p02=0.f,p03=0.f;
        float p10=0.f,p11=0.f,p12=0.f,p13=0.f;
        int ibeg = ig*12;
        #pragma unroll
        for (int i = ibeg; i < ibeg + 12; ++i) {
            uint2 raw = __ldg(&r2p[i*32]);
            float2 v0 = __half22float2(*(__half2*)&raw.x);
            float2 v1 = __half22float2(*(__half2*)&raw.y);
            float2 aa = *(float2*)&a_s[i][0];
            p00 += aa.x*v0.x; p01 += aa.x*v0.y; p02 += aa.x*v1.x; p03 += aa.x*v1.y;
            p10 += aa.y*v0.x; p11 += aa.y*v0.y; p12 += aa.y*v1.x; p13 += aa.y*v1.y;
        }
        Pp[ig][2*tq]   = make_float4(p00, p10, p01, p11);
        Pp[ig][2*tq+1] = make_float4(p02, p12, p03, p13);
    } else if (t < 130) {
        int s = t - 128;
        float q = 0.f;
        #pragma unroll
        for (int i = 0; i < 48; ++i) q += a_s[i][s];
        Qs[s] = q;
    }
    __syncthreads();
    if (t < 64) {
        float4 A = Pp[0][t], B = Pp[1][t], C = Pp[2][t], D = Pp[3][t];
        Pq[t] = make_float4(A.x+B.x+C.x+D.x, A.y+B.y+C.y+D.y,
                            A.z+B.z+C.z+D.z, A.w+B.w+C.w+D.w);
    }
    __syncthreads();

    if (t < 128) {
        int m = t & 63, half = t >> 6;
        const uint4* SPh = d_SPh + (sel*32)*64 + m;
        float acc = 0.f;
        int cb = half*16;
        #pragma unroll 4
        for (int cq2 = cb; cq2 < cb + 16; ++cq2) {
            uint4 raw = __ldg(&SPh[cq2*64]);
            __half2* hp = (__half2*)&raw;
            float2 s0 = __half22float2(hp[0]);
            float2 s1 = __half22float2(hp[1]);
            float2 s2 = __half22float2(hp[2]);
            float2 s3 = __half22float2(hp[3]);
            float4 pA = Pq[2*cq2], pB = Pq[2*cq2+1];
            acc += s0.x*pA.x + s0.y*pA.y + s1.x*pA.z + s1.y*pA.w
                 + s2.x*pB.x + s2.y*pB.y + s3.x*pB.z + s3.y*pB.w;
        }
        part[half][m] = acc;
    }
    __syncthreads();
    if (t < 64) {
        float2 bp = __ldg(&d_SPb[sel*64 + t]);
        ((float*)aggq)[t] = part[0][t] + part[1][t] + bp.x*Qs[0] + bp.y*Qs[1];
    }
    __syncthreads();

    {
        int gc = t;
        float acc = 0.f;
        #pragma unroll 4
        for (int kq2 = 0; kq2 < 8; ++kq2) {
            uint4 raw = __ldg(&d_wihh[kq2*192 + gc]);
            __half2* hp = (__half2*)&raw;
            float2 w0 = __half22float2(hp[0]);
            float2 w1 = __half22float2(hp[1]);
            float2 w2 = __half22float2(hp[2]);
            float2 w3 = __half22float2(hp[3]);
            float4 a0 = aggq[2*kq2], a1 = aggq[2*kq2+1];
            acc += w0.x*a0.x + w0.y*a0.y + w1.x*a0.z + w1.y*a0.w
                 + w2.x*a1.x + w2.y*a1.y + w3.x*a1.z + w3.y*a1.w;
        }
        gis[gc] = acc;
    }
    __syncthreads();

    if (t < 64) {
        int c = t;
        float gh0 = __ldg(&d_gh[bj*192 + c]);
        float gh1 = __ldg(&d_gh[bj*192 + 64 + c]);
        float gh2 = __ldg(&d_gh[bj*192 + 128 + c]);
        float r = 1.f/(1.f+expf(-(gis[c]      + bih[c]      + gh0)));
        float z = 1.f/(1.f+expf(-(gis[64+c]   + bih[64+c]   + gh1)));
        float n = tanhf(gis[128+c] + bih[128+c] + r*gh2);
        float hn = (1.f-z)*n + z*hold[c];
        float hm = d_mask[bj]*hn;
        h_out[bj*64 + c] = hm;
        h_outT[c*768 + bj] = hm;
        ((float*)hnq)[c] = hm;
    }
    if (!last) {
        __syncthreads();
        int gc = t;
        float acc = 0.f;
        #pragma unroll 4
        for (int kq2 = 0; kq2 < 8; ++kq2) {
            uint4 raw = __ldg(&d_whhh[kq2*192 + gc]);
            __half2* hp = (__half2*)&raw;
            float2 w0 = __half22float2(hp[0]);
            float2 w1 = __half22float2(hp[1]);
            float2 w2 = __half22float2(hp[2]);
            float2 w3 = __half22float2(hp[3]);
            float4 h0q = hnq[2*kq2], h1q = hnq[2*kq2+1];
            acc += w0.x*h0q.x + w0.y*h0q.y + w1.x*h0q.z + w1.y*h0q.w
                 + w2.x*h1q.x + w2.y*h1q.y + w3.x*h1q.z + w3.y*h1q.w;
        }
        d_gh[bj*192 + gc] = acc + bhh[gc];
    }
}

// -------- readout + fused final reduction (ticket pattern) --------
__global__ void __launch_bounds__(128) readout_kernel(
   const float* __restrict__ r0b0, const float* __restrict__ r0b1,
   const float* __restrict__ r0b2, const float* __restrict__ r1b0,
   const float* __restrict__ r1b1, const float* __restrict__ r1b2,
   float* __restrict__ out) {
    __shared__ float4 xinv[128];
    __shared__ float4 bufA[128];
    __shared__ float4 bufB[128];
    __shared__ unsigned ticket;
    int c = threadIdx.x;
    int n0 = blockIdx.x * 4;
    int bb = blockIdx.x / 12;   // batch this CTA belongs to
    {
        float v[4];
        #pragma unroll
        for (int r = 0; r < 4; ++r)
            v[r] = (c < 64) ? d_hf[(n0+r)*64 + c] : d_hA[(n0+r)*64 + (c-64)];
        xinv[c] = make_float4(v[0], v[1], v[2], v[3]);
    }
    __syncthreads();

    float4 acc;
    { float b = r0b0[c]; acc = make_float4(b,b,b,b); }
    #pragma unroll 4
    for (int kq2 = 0; kq2 < 16; ++kq2)
        ro_step(acc, __ldg(&d_q0w0h[kq2*128 + c]), &xinv[8*kq2]);
    bufA[c] = make_float4(fmaxf(acc.x,0.f), fmaxf(acc.y,0.f), fmaxf(acc.z,0.f), fmaxf(acc.w,0.f));
    __syncthreads();
    { float b = r0b1[c]; acc = make_float4(b,b,b,b); }
    #pragma unroll 4
    for (int kq2 = 0; kq2 < 16; ++kq2)
        ro_step(acc, __ldg(&d_q0w1h[kq2*128 + c]), &bufA[8*kq2]);
    bufB[c] = make_float4(fmaxf(acc.x,0.f), fmaxf(acc.y,0.f), fmaxf(acc.z,0.f), fmaxf(acc.w,0.f));
    __syncthreads();
    float4 out0;
    { float b = r0b2[c]; out0 = make_float4(b,b,b,b); }
    #pragma unroll 4
    for (int kq2 = 0; kq2 < 16; ++kq2)
        ro_step(out0, __ldg(&d_q0w2h[kq2*128 + c]), &bufB[8*kq2]);
    { float b = r1b0[c]; acc = make_float4(b,b,b,b); }
    #pragma unroll 4
    for (int kq2 = 0; kq2 < 8; ++kq2)
        ro_step(acc, __ldg(&d_q1w0h[kq2*128 + c]), &xinv[64 + 8*kq2]);
    __syncthreads();
    bufA[c] = make_float4(fmaxf(acc.x,0.f), fmaxf(acc.y,0.f), fmaxf(acc.z,0.f), fmaxf(acc.w,0.f));
    __syncthreads();
    { float b = r1b1[c]; acc = make_float4(b,b,b,b); }
    #pragma unroll 4
    for (int kq2 = 0; kq2 < 16; ++kq2)
        ro_step(acc, __ldg(&d_q1w1h[kq2*128 + c]), &bufA[8*kq2]);
    __syncthreads();
    bufB[c] = make_float4(fmaxf(acc.x,0.f), fmaxf(acc.y,0.f), fmaxf(acc.z,0.f), fmaxf(acc.w,0.f));
    __syncthreads();
    float4 out1;
    { float b = r1b2[c]; out1 = make_float4(b,b,b,b); }
    #pragma unroll 4
    for (int kq2 = 0; kq2 < 16; ++kq2)
        ro_step(out1, __ldg(&d_q1w2h[kq2*128 + c]), &bufB[8*kq2]);
    d_tmp[(n0+0)*128 + c] = d_mask[n0+0]*out0.x*out1.x;
    d_tmp[(n0+1)*128 + c] = d_mask[n0+1]*out0.y*out1.y;
    d_tmp[(n0+2)*128 + c] = d_mask[n0+2]*out0.z*out1.z;
    d_tmp[(n0+3)*128 + c] = d_mask[n0+3]*out0.w*out1.w;

    // ---- fused reduction: last CTA of each batch sums + sigmoid ----
    __threadfence();
    __syncthreads();
    if (c == 0) ticket = atomicAdd(&d_cnt[bb], 1u);
    __syncthreads();
    if (ticket == 11u) {
        float s = 0.f;
        const float* tp = d_tmp + (size_t)bb*48*128 + c;
        #pragma unroll 8
        for (int jj = 0; jj < 48; ++jj)
            s += __ldcg(tp + jj*128);
        out[bb*128 + c] = 1.f/(1.f+expf(-s));
    }
}

extern "C" void kernel_launch(void* const* d_in, const int* in_sizes, int n_in,
                              void* d_out, int out_size) {
    const float* g       = (const float*)d_in[0];
    const float* h0      = (const float*)d_in[1];
    const float* e       = (const float*)d_in[2];
    const float* msg_w0  = (const float*)d_in[3];
    const float* msg_b0  = (const float*)d_in[4];
    const float* msg_w1  = (const float*)d_in[5];
    const float* msg_b1  = (const float*)d_in[6];
    const float* msg_w2  = (const float*)d_in[7];
    const float* msg_b2  = (const float*)d_in[8];
    const float* gru_wih = (const float*)d_in[9];
    const float* gru_whh = (const float*)d_in[10];
    const float* gru_bih = (const float*)d_in[11];
    const float* gru_bhh = (const float*)d_in[12];
    const float* r0_w0   = (const float*)d_in[13];
    const float* r0_b0   = (const float*)d_in[14];
    const float* r0_w1   = (const float*)d_in[15];
    const float* r0_b1   = (const float*)d_in[16];
    const float* r0_w2   = (const float*)d_in[17];
    const float* r0_b2   = (const float*)d_in[18];
    const float* r1_w0   = (const float*)d_in[19];
    const float* r1_b0   = (const float*)d_in[20];
    const float* r1_w1   = (const float*)d_in[21];
    const float* r1_b1   = (const float*)d_in[22];
    const float* r1_w2   = (const float*)d_in[23];
    const float* r1_b2   = (const float*)d_in[24];
    float* out = (float*)d_out;

    cudaFuncSetAttribute(relu2_kernel, cudaFuncAttributeMaxDynamicSharedMemorySize, RELU2_SMEM);

    megaprep_kernel<<<495, 192>>>(msg_w2, msg_b2, gru_wih, gru_whh, gru_bhh,
                                  msg_w1, msg_w0, h0, g,
                                  r0_w0, r0_w1, r0_w2, r1_w0, r1_w1, r1_w2);
    relu2_kernel<<<NE/128, 256, RELU2_SMEM>>>(e, msg_b0, msg_b1);
    // L1: hf -> hA ; L2: hA -> hB ; L3: hB -> hA
    layer_kernel<<<dim3(48, 16), 192>>>(0, 1, 0, gru_bih, gru_bhh);
    layer_kernel<<<dim3(48, 16), 192>>>(1, 2, 0, gru_bih, gru_bhh);
    layer_kernel<<<dim3(48, 16), 192>>>(2, 1, 1, gru_bih, gru_bhh);
    readout_kernel<<<NNODE/4, 128>>>(r0_b0, r0_b1, r0_b2, r1_b0, r1_b1, r1_b2, out);
}

// round 17
// speedup vs baseline: 1.1971x; 1.1324x over previous
#include <cuda_runtime.h>
#include <cuda_fp16.h>
#include <math.h>

#define NB 16
#define NN 48
#define HID 64
#define MSG 64
#define EDGE 16
#define NL 128
#define TGT 128
#define NE (NB*NN*NN)    // 36864 edges
#define NNODE (NB*NN)    // 768 nodes

// -------- device scratch (static; no allocation) --------
__device__ uint4 d_SPh[3*32*64];     // fp16 SP: [sel][cq2][m] = 8 halfs
__device__ float2 d_SPb[3*64];       // bias prefix row [sel][m] (fp32)
__device__ uint4 d_wihh[8*192];      // fp16 wih: [kq2][gc]
__device__ uint4 d_whhh[8*192];      // fp16 whh
__device__ __half d_w1t[NL*NL];      // msg_w1 transposed [n][k], fp16
__device__ __half d_w0t[NL*EDGE];    // msg_w0 transposed [n][k], fp16
__device__ __half d_r2h[NE*NL];      // relu2 fp16, TRANSPOSED: [(b*48+j)*48+i][c]
__device__ float d_gT[NNODE*NN];     // g transposed: [b*48+j][i]
__device__ float d_hf[NNODE*HID];    // h_first (normal layout)
__device__ float d_hA[NNODE*HID];
__device__ float d_hB[NNODE*HID];
__device__ float d_hfT[HID*NNODE];   // transposed: [c][node]
__device__ float d_hAT[HID*NNODE];
__device__ float d_hBT[HID*NNODE];
__device__ float d_gh[NNODE*192];    // initial hidden gates from megaprep (incl. bhh)
__device__ float d_mask[NNODE];
__device__ float d_tmp[NNODE*TGT];
__device__ unsigned d_bar;           // grid barrier counter
// readout weights, fp16-packed over k-octets: [kq2][c] = 8 halfs
__device__ uint4 d_q0w0h[16*128];
__device__ uint4 d_q0w1h[16*128];
__device__ uint4 d_q0w2h[16*128];
__device__ uint4 d_q1w0h[8*128];
__device__ uint4 d_q1w1h[16*128];
__device__ uint4 d_q1w2h[16*128];

#define MMA_F16(c0,c1,c2,c3,a0,a1,a2,a3,b0,b1) \
  asm volatile("mma.sync.aligned.m16n8k16.row.col.f32.f16.f16.f32 " \
    "{%0,%1,%2,%3},{%4,%5,%6,%7},{%8,%9},{%0,%1,%2,%3};" \
    : "+f"(c0),"+f"(c1),"+f"(c2),"+f"(c3) \
    : "r"(a0),"r"(a1),"r"(a2),"r"(a3),"r"(b0),"r"(b1))

// readout fp16-weight step: 8 k-values per uint4, 4 nodes wide
__device__ __forceinline__ void ro_step(float4& acc, uint4 raw, const float4* xv) {
    __half2* hp = (__half2*)&raw;
    #pragma unroll
    for (int q = 0; q < 4; ++q) {
        float2 w = __half22float2(hp[q]);
        float4 xa = xv[2*q], xb = xv[2*q+1];
        acc.x += w.x*xa.x + w.y*xb.x;
        acc.y += w.x*xa.y + w.y*xb.y;
        acc.z += w.x*xa.z + w.y*xb.z;
        acc.w += w.x*xa.w + w.y*xb.w;
    }
}

// software grid barrier (all 768 CTAs co-resident by construction)
__device__ __forceinline__ void grid_barrier(unsigned target) {
    __threadfence();
    __syncthreads();
    if (threadIdx.x == 0) {
        atomicAdd(&d_bar, 1u);
        while (*((volatile unsigned*)&d_bar) < target) { }
    }
    __syncthreads();
}

// -------- mega-prep (R13 + d_bar zeroing) --------
__global__ void __launch_bounds__(192) megaprep_kernel(
        const float* __restrict__ w2, const float* __restrict__ b2,
        const float* __restrict__ wih, const float* __restrict__ whh,
        const float* __restrict__ bhh,
        const float* __restrict__ w1, const float* __restrict__ w0,
        const float* __restrict__ h0, const float* __restrict__ g,
        const float* __restrict__ r0w0, const float* __restrict__ r0w1,
        const float* __restrict__ r0w2, const float* __restrict__ r1w0,
        const float* __restrict__ r1w1, const float* __restrict__ r1w2) {
    int blk = blockIdx.x;
    int t = threadIdx.x;
    if (blk < 128) {
        if (t < 64) {
            int c = blk, m = t;
            const float* p = w2 + c*4096 + m*64;
            float acc = 0.f, s16 = 0.f, s32 = 0.f, s48 = 0.f;
            #pragma unroll
            for (int h = 0; h < 64; ++h) {
                acc += p[h];
                if (h == 15) s16 = acc;
                if (h == 31) s32 = acc;
                if (h == 47) s48 = acc;
            }
            int cq2 = c >> 2, pos = (c & 3)*2;
            __half* base = (__half*)d_SPh;
            base[(((0*32 + cq2)*64 + m))*8 + pos    ] = __float2half(s16);
            base[(((0*32 + cq2)*64 + m))*8 + pos + 1] = __float2half(acc - s16);
            base[(((1*32 + cq2)*64 + m))*8 + pos    ] = __float2half(s32);
            base[(((1*32 + cq2)*64 + m))*8 + pos + 1] = __float2half(acc - s32);
            base[(((2*32 + cq2)*64 + m))*8 + pos    ] = __float2half(s48);
            base[(((2*32 + cq2)*64 + m))*8 + pos + 1] = __float2half(acc - s48);
        }
    } else if (blk == 128) {
        if (t < 64) {
            int m = t;
            const float* q = b2 + m*64;
            float a = 0.f, t16 = 0.f, t32 = 0.f, t48 = 0.f;
            #pragma unroll
            for (int h = 0; h < 64; ++h) {
                a += q[h];
                if (h == 15) t16 = a;
                if (h == 31) t32 = a;
                if (h == 47) t48 = a;
            }
            d_SPb[0*64+m] = make_float2(t16, a - t16);
            d_SPb[1*64+m] = make_float2(t32, a - t32);
            d_SPb[2*64+m] = make_float2(t48, a - t48);
        }
        if (t == 64) d_bar = 0u;
    } else if (blk < 137) {
        int kq2 = blk - 129;
        __align__(16) __half hb[8];
        #pragma unroll
        for (int q = 0; q < 8; ++q) hb[q] = __float2half(wih[t*64 + 8*kq2 + q]);
        d_wihh[kq2*192 + t] = *(uint4*)hb;
    } else if (blk < 145) {
        int kq2 = blk - 137;
        __align__(16) __half hb[8];
        #pragma unroll
        for (int q = 0; q < 8; ++q) hb[q] = __float2half(whh[t*64 + 8*kq2 + q]);
        d_whhh[kq2*192 + t] = *(uint4*)hb;
    } else if (blk < 151) {
        int mat = blk - 145;
        const float* src; uint4* dst; int nkq2;
        if (mat == 0)      { src = r0w0; dst = d_q0w0h; nkq2 = 16; }
        else if (mat == 1) { src = r0w1; dst = d_q0w1h; nkq2 = 16; }
        else if (mat == 2) { src = r0w2; dst = d_q0w2h; nkq2 = 16; }
        else if (mat == 3) { src = r1w0; dst = d_q1w0h; nkq2 = 8; }
        else if (mat == 4) { src = r1w1; dst = d_q1w1h; nkq2 = 16; }
        else               { src = r1w2; dst = d_q1w2h; nkq2 = 16; }
        int total = nkq2 * 128;
        for (int idx = t; idx < total; idx += 192) {
            int kq2 = idx >> 7, c = idx & 127;
            __align__(16) __half hb[8];
            #pragma unroll
            for (int q = 0; q < 8; ++q)
                hb[q] = __float2half(src[(8*kq2+q)*128 + c]);
            dst[idx] = *(uint4*)hb;
        }
    } else if (blk < 407) {
        int nb = blk - 151;
        int node = nb*3 + t/64;
        int c = t & 63;
        __shared__ float red[192];
        float v = (c < 32) ? h0[node*32 + c] : 0.f;
        d_hf[node*64 + c] = v;
        d_hfT[c*768 + node] = v;
        red[t] = v;
        __syncthreads();
        if (c == 0) {
            float s = 0.f;
            int b0 = (t/64)*64;
            #pragma unroll
            for (int i = 0; i < 32; ++i) s += red[b0 + i];
            d_mask[node] = (s > 0.f) ? 1.f : 0.f;
        }
        int gc = t;
        float bh = bhh[gc];
        #pragma unroll
        for (int nn = 0; nn < 3; ++nn) {
            float acc = 0.f;
            #pragma unroll 4
            for (int kq = 0; kq < 16; ++kq) {
                float4 w = *(const float4*)&whh[gc*64 + 4*kq];
                acc += w.x*red[nn*64 + 4*kq]   + w.y*red[nn*64 + 4*kq+1]
                     + w.z*red[nn*64 + 4*kq+2] + w.w*red[nn*64 + 4*kq+3];
            }
            d_gh[(nb*3 + nn)*192 + gc] = acc + bh;
        }
    } else if (blk < 423) {
        int base = (blk - 407)*2304;
        for (int r = t; r < 2304; r += 192) {
            int gidx = base + r;
            int bj = gidx / 48, i = gidx % 48;
            int b = bj / 48, j = bj % 48;
            d_gT[gidx] = g[(b*48 + i)*48 + j];
        }
    } else if (blk < 487) {
        int base = (blk - 423)*256;
        for (int idx = t; idx < 256; idx += 192) {
            int i = base + idx;
            int n = i >> 7, k = i & 127;
            d_w1t[i] = __float2half(w1[k*128 + n]);
        }
    } else {
        int base = (blk - 487)*256;
        for (int idx = t; idx < 256; idx += 192) {
            int i = base + idx;
            int n = i >> 4, k = i & 15;
            d_w0t[i] = __float2half(w0[k*128 + n]);
        }
    }
}

// -------- edge MLP via fp16 tensor cores (unchanged from R13) --------
#define RELU2_SMEM ((128*136*2 + 128*16*2)*2 + 256*4)
__global__ void __launch_bounds__(256) relu2_kernel(const float* __restrict__ e,
        const float* __restrict__ b0, const float* __restrict__ b1) {
    extern __shared__ char smem_raw[];
    __half* W1H = (__half*)smem_raw;
    __half* X1H = W1H + 128*136;
    __half* ESH = X1H + 128*136;
    __half* W0H = ESH + 128*16;
    float* B0S = (float*)(W0H + 128*16);
    float* B1S = B0S + 128;
    int t = threadIdx.x;
    int row0 = blockIdx.x * 128;

    {
        const uint4* w1v = (const uint4*)d_w1t;
        for (int idx = t; idx < 2048; idx += 256) {
            int n = idx >> 4, kq = idx & 15;
            *(uint4*)&W1H[n*136 + kq*8] = __ldg(&w1v[idx]);
        }
        const float4* ev = (const float4*)(e + row0*16);
        for (int idx = t; idx < 512; idx += 256) {
            float4 x = __ldg(&ev[idx]);
            int r = idx >> 2, kq = idx & 3;
            uint2 u;
            __half2 h0 = __floats2half2_rn(x.x, x.y);
            __half2 h1 = __floats2half2_rn(x.z, x.w);
            u.x = *(unsigned*)&h0; u.y = *(unsigned*)&h1;
            *(uint2*)&ESH[r*16 + kq*4] = u;
        }
        const uint4* w0v = (const uint4*)d_w0t;
        if (t < 256) {
            int n = t >> 1, hq = t & 1;
            *(uint4*)&W0H[n*16 + hq*8] = __ldg(&w0v[t]);
        }
        if (t < 128) { B0S[t] = b0[t]; B1S[t] = b1[t]; }
    }
    __syncthreads();

    int lane = t & 31, warp = t >> 5;
    int rbase = warp * 16;
    int grp = lane >> 2, tig = lane & 3;

    float acc[16][4];
    #pragma unroll
    for (int nt = 0; nt < 16; ++nt) {
        float bv0 = B0S[nt*8 + 2*tig], bv1 = B0S[nt*8 + 2*tig + 1];
        acc[nt][0] = bv0; acc[nt][1] = bv1; acc[nt][2] = bv0; acc[nt][3] = bv1;
    }
    {
        unsigned a0 = *(unsigned*)&ESH[(rbase+grp  )*16 + 2*tig];
        unsigned a1 = *(unsigned*)&ESH[(rbase+grp+8)*16 + 2*tig];
        unsigned a2 = *(unsigned*)&ESH[(rbase+grp  )*16 + 8 + 2*tig];
        unsigned a3 = *(unsigned*)&ESH[(rbase+grp+8)*16 + 8 + 2*tig];
        #pragma unroll
        for (int nt = 0; nt < 16; ++nt) {
            unsigned bb0 = *(unsigned*)&W0H[(nt*8+grp)*16 + 2*tig];
            unsigned bb1 = *(unsigned*)&W0H[(nt*8+grp)*16 + 8 + 2*tig];
            MMA_F16(acc[nt][0],acc[nt][1],acc[nt][2],acc[nt][3],a0,a1,a2,a3,bb0,bb1);
        }
    }
    #pragma unroll
    for (int nt = 0; nt < 16; ++nt) {
        __half2 lo = __floats2half2_rn(fmaxf(acc[nt][0],0.f), fmaxf(acc[nt][1],0.f));
        __half2 hi = __floats2half2_rn(fmaxf(acc[nt][2],0.f), fmaxf(acc[nt][3],0.f));
        *(__half2*)&X1H[(rbase+grp  )*136 + nt*8 + 2*tig] = lo;
        *(__half2*)&X1H[(rbase+grp+8)*136 + nt*8 + 2*tig] = hi;
    }
    __syncthreads();

    #pragma unroll
    for (int nt = 0; nt < 16; ++nt) {
        float bv0 = B1S[nt*8 + 2*tig], bv1 = B1S[nt*8 + 2*tig + 1];
        acc[nt][0] = bv0; acc[nt][1] = bv1; acc[nt][2] = bv0; acc[nt][3] = bv1;
    }
    #pragma unroll
    for (int kt = 0; kt < 8; ++kt) {
        unsigned a0 = *(unsigned*)&X1H[(rbase+grp  )*136 + kt*16 + 2*tig];
        unsigned a1 = *(unsigned*)&X1H[(rbase+grp+8)*136 + kt*16 + 2*tig];
        unsigned a2 = *(unsigned*)&X1H[(rbase+grp  )*136 + kt*16 + 8 + 2*tig];
        unsigned a3 = *(unsigned*)&X1H[(rbase+grp+8)*136 + kt*16 + 8 + 2*tig];
        #pragma unroll
        for (int nt = 0; nt < 16; ++nt) {
            unsigned bb0 = *(unsigned*)&W1H[(nt*8+grp)*136 + kt*16 + 2*tig];
            unsigned bb1 = *(unsigned*)&W1H[(nt*8+grp)*136 + kt*16 + 8 + 2*tig];
            MMA_F16(acc[nt][0],acc[nt][1],acc[nt][2],acc[nt][3],a0,a1,a2,a3,bb0,bb1);
        }
    }
    __syncthreads();

    __half2* H = (__half2*)X1H;
    #pragma unroll
    for (int nt = 0; nt < 16; ++nt) {
        H[(rbase+grp  )*68 + nt*4 + tig] =
            __floats2half2_rn(fmaxf(acc[nt][0],0.f), fmaxf(acc[nt][1],0.f));
        H[(rbase+grp+8)*68 + nt*4 + tig] =
            __floats2half2_rn(fmaxf(acc[nt][2],0.f), fmaxf(acc[nt][3],0.f));
    }
    __syncthreads();
    for (int idx = t; idx < 2048; idx += 256) {
        int r = idx >> 4, chunk = idx & 15;
        int row = row0 + r;
        int b = row / 2304; int rem = row - b*2304;
        int i = rem / 48;   int j = rem - i*48;
        uint4 v = *(const uint4*)((const char*)X1H + (size_t)r*272 + chunk*16);
        *(uint4*)(d_r2h + (size_t)((b*48 + j)*48 + i)*128 + chunk*8) = v;
    }
}

// -------- persistent mega-layer: 3 layers + readout + reduce, one launch --------
__global__ void __launch_bounds__(192, 6) megalayer_kernel(
        const float* __restrict__ bih, const float* __restrict__ bhh,
        const float* __restrict__ r0b0, const float* __restrict__ r0b1,
        const float* __restrict__ r0b2, const float* __restrict__ r1b0,
        const float* __restrict__ r1b1, const float* __restrict__ r1b2,
        float* __restrict__ out) {
    int blk = blockIdx.x;      // 0..767
    int t = threadIdx.x;
    int j = blk % 48, b = blk / 48;
    int bj = blk;              // b*48 + j == blk
    int k0 = (4*j)/3;
    int a64 = (16*j) % 48;
    int sel = (48 - a64)/16 - 1;

    __shared__ float a_s[48][2];
    __shared__ float gS[48];
    __shared__ __align__(16) float hold[64];
    __shared__ float4 Pp[4][64];
    __shared__ float4 Pq[64];
    __shared__ float part[2][64];
    __shared__ float4 aggq[16];
    __shared__ float gis[192];
    __shared__ float ghs[192];
    __shared__ float Qs[2];
    __shared__ float maskS;
    // readout
    __shared__ float4 xinv[128];
    __shared__ float4 bufA[128];
    __shared__ float4 bufB[128];

    const float* hinT = d_hfT;
    float* hout  = d_hA;
    float* houtT = d_hAT;

    #pragma unroll 1
    for (int L = 0; L < 3; ++L) {
        // ---- Phase A ----
        if (t < 96) {
            int s = t / 48, i = t % 48;
            float gv;
            if (L == 0) {
                gv = __ldg(&d_gT[bj*48 + i]);
                if (s == 0) gS[i] = gv;
            } else gv = gS[i];
            a_s[i][s] = gv * __ldcg(&hinT[(k0+s)*768 + b*48 + i]);
        } else if (t < 160) {
            if (L == 0) hold[t - 96] = __ldcg(&d_hf[bj*64 + (t - 96)]);
        } else if (t == 160 && L == 0) {
            maskS = d_mask[bj];
        }
        if (L == 0) ghs[t] = __ldg(&d_gh[bj*192 + t]);
        __syncthreads();

        // ---- Phase B: P partials ----
        if (t < 128) {
            int tq = t & 31, ig = t >> 5;
            const uint2* r2p = (const uint2*)(d_r2h + (size_t)bj*6144) + tq;
            float p00=0.f,p01=0.f,p02=0.f,p03=0.f;
            float p10=0.f,p11=0.f,p12=0.f,p13=0.f;
            int ibeg = ig*12;
            #pragma unroll
            for (int i = ibeg; i < ibeg + 12; ++i) {
                uint2 raw = __ldg(&r2p[i*32]);
                float2 v0 = __half22float2(*(__half2*)&raw.x);
                float2 v1 = __half22float2(*(__half2*)&raw.y);
                float2 aa = *(float2*)&a_s[i][0];
                p00 += aa.x*v0.x; p01 += aa.x*v0.y; p02 += aa.x*v1.x; p03 += aa.x*v1.y;
                p10 += aa.y*v0.x; p11 += aa.y*v0.y; p12 += aa.y*v1.x; p13 += aa.y*v1.y;
            }
            Pp[ig][2*tq]   = make_float4(p00, p10, p01, p11);
            Pp[ig][2*tq+1] = make_float4(p02, p12, p03, p13);
        } else if (t < 130) {
            int s = t - 128;
            float q = 0.f;
            #pragma unroll
            for (int i = 0; i < 48; ++i) q += a_s[i][s];
            Qs[s] = q;
        }
        __syncthreads();
        if (t < 64) {
            float4 A = Pp[0][t], B = Pp[1][t], C = Pp[2][t], D = Pp[3][t];
            Pq[t] = make_float4(A.x+B.x+C.x+D.x, A.y+B.y+C.y+D.y,
                                A.z+B.z+C.z+D.z, A.w+B.w+C.w+D.w);
        }
        __syncthreads();

        // ---- Phase C ----
        if (t < 128) {
            int m = t & 63, half = t >> 6;
            const uint4* SPh = d_SPh + (sel*32)*64 + m;
            float acc = 0.f;
            int cb = half*16;
            #pragma unroll 4
            for (int cq2 = cb; cq2 < cb + 16; ++cq2) {
                uint4 raw = __ldg(&SPh[cq2*64]);
                __half2* hp = (__half2*)&raw;
                float2 s0 = __half22float2(hp[0]);
                float2 s1 = __half22float2(hp[1]);
                float2 s2 = __half22float2(hp[2]);
                float2 s3 = __half22float2(hp[3]);
                float4 pA = Pq[2*cq2], pB = Pq[2*cq2+1];
                acc += s0.x*pA.x + s0.y*pA.y + s1.x*pA.z + s1.y*pA.w
                     + s2.x*pB.x + s2.y*pB.y + s3.x*pB.z + s3.y*pB.w;
            }
            part[half][m] = acc;
        }
        __syncthreads();
        if (t < 64) {
            float2 bp = __ldg(&d_SPb[sel*64 + t]);
            ((float*)aggq)[t] = part[0][t] + part[1][t] + bp.x*Qs[0] + bp.y*Qs[1];
        }
        __syncthreads();

        // ---- Phase D ----
        {
            int gc = t;
            float acc = 0.f;
            #pragma unroll 4
            for (int kq2 = 0; kq2 < 8; ++kq2) {
                uint4 raw = __ldg(&d_wihh[kq2*192 + gc]);
                __half2* hp = (__half2*)&raw;
                float2 w0 = __half22float2(hp[0]);
                float2 w1 = __half22float2(hp[1]);
                float2 w2 = __half22float2(hp[2]);
                float2 w3 = __half22float2(hp[3]);
                float4 a0 = aggq[2*kq2], a1 = aggq[2*kq2+1];
                acc += w0.x*a0.x + w0.y*a0.y + w1.x*a0.z + w1.y*a0.w
                     + w2.x*a1.x + w2.y*a1.y + w3.x*a1.z + w3.y*a1.w;
            }
            gis[gc] = acc;
        }
        __syncthreads();

        // ---- Phase E1: GRU combine (ghs/hold in smem) ----
        if (t < 64) {
            int c = t;
            float r = 1.f/(1.f+expf(-(gis[c]      + bih[c]      + ghs[c])));
            float z = 1.f/(1.f+expf(-(gis[64+c]   + bih[64+c]   + ghs[64+c])));
            float n = tanhf(gis[128+c] + bih[128+c] + r*ghs[128+c]);
            float hn = (1.f-z)*n + z*hold[c];
            float hm = maskS*hn;
            hout[bj*64 + c] = hm;
            houtT[c*768 + bj] = hm;
            hold[c] = hm;
        }
        if (L < 2) {
            __syncthreads();
            // ---- Phase E2: next-layer gh into smem ----
            int gc = t;
            float acc = 0.f;
            #pragma unroll 4
            for (int kq2 = 0; kq2 < 8; ++kq2) {
                uint4 raw = __ldg(&d_whhh[kq2*192 + gc]);
                __half2* hp = (__half2*)&raw;
                float2 w0 = __half22float2(hp[0]);
                float2 w1 = __half22float2(hp[1]);
                float2 w2 = __half22float2(hp[2]);
                float2 w3 = __half22float2(hp[3]);
                float4 h0q = ((const float4*)hold)[2*kq2], h1q = ((const float4*)hold)[2*kq2+1];
                acc += w0.x*h0q.x + w0.y*h0q.y + w1.x*h0q.z + w1.y*h0q.w
                     + w2.x*h1q.x + w2.y*h1q.y + w3.x*h1q.z + w3.y*h1q.w;
            }
            ghs[gc] = acc + bhh[gc];
        }
        grid_barrier((unsigned)(L+1)*768u);
        // swap buffers
        if (L == 0) { hinT = d_hAT; hout = d_hB; houtT = d_hBT; }
        else        { hinT = d_hBT; hout = d_hA; houtT = d_hAT; }
    }

    // ---- readout: CTAs 0..191, 4 nodes each ----
    if (blk < 192) {
        int c = t & 127;
        int n0 = blk * 4;
        if (t < 128) {
            float v[4];
            #pragma unroll
            for (int r = 0; r < 4; ++r)
                v[r] = (c < 64) ? __ldcg(&d_hf[(n0+r)*64 + c])
                                : __ldcg(&d_hA[(n0+r)*64 + (c-64)]);
            xinv[c] = make_float4(v[0], v[1], v[2], v[3]);
        }
        __syncthreads();
        float4 acc, out0, out1;
        if (t < 128) {
            { float bb = r0b0[c]; acc = make_float4(bb,bb,bb,bb); }
            #pragma unroll 4
            for (int kq2 = 0; kq2 < 16; ++kq2)
                ro_step(acc, __ldg(&d_q0w0h[kq2*128 + c]), &xinv[8*kq2]);
        }
        __syncthreads();
        if (t < 128)
            bufA[c] = make_float4(fmaxf(acc.x,0.f), fmaxf(acc.y,0.f), fmaxf(acc.z,0.f), fmaxf(acc.w,0.f));
        __syncthreads();
        if (t < 128) {
            { float bb = r0b1[c]; acc = make_float4(bb,bb,bb,bb); }
            #pragma unroll 4
            for (int kq2 = 0; kq2 < 16; ++kq2)
                ro_step(acc, __ldg(&d_q0w1h[kq2*128 + c]), &bufA[8*kq2]);
        }
        __syncthreads();
        if (t < 128)
            bufB[c] = make_float4(fmaxf(acc.x,0.f), fmaxf(acc.y,0.f), fmaxf(acc.z,0.f), fmaxf(acc.w,0.f));
        __syncthreads();
        if (t < 128) {
            { float bb = r0b2[c]; out0 = make_float4(bb,bb,bb,bb); }
            #pragma unroll 4
            for (int kq2 = 0; kq2 < 16; ++kq2)
                ro_step(out0, __ldg(&d_q0w2h[kq2*128 + c]), &bufB[8*kq2]);
            { float bb = r1b0[c]; acc = make_float4(bb,bb,bb,bb); }
            #pragma unroll 4
            for (int kq2 = 0; kq2 < 8; ++kq2)
                ro_step(acc, __ldg(&d_q1w0h[kq2*128 + c]), &xinv[64 + 8*kq2]);
        }
        __syncthreads();
        if (t < 128)
            bufA[c] = make_float4(fmaxf(acc.x,0.f), fmaxf(acc.y,0.f), fmaxf(acc.z,0.f), fmaxf(acc.w,0.f));
        __syncthreads();
        if (t < 128) {
            { float bb = r1b1[c]; acc = make_float4(bb,bb,bb,bb); }
            #pragma unroll 4
            for (int kq2 = 0; kq2 < 16; ++kq2)
                ro_step(acc, __ldg(&d_q1w1h[kq2*128 + c]), &bufA[8*kq2]);
        }
        __syncthreads();
        if (t < 128)
            bufB[c] = make_float4(fmaxf(acc.x,0.f), fmaxf(acc.y,0.f), fmaxf(acc.z,0.f), fmaxf(acc.w,0.f));
        __syncthreads();
        if (t < 128) {
            { float bb = r1b2[c]; out1 = make_float4(bb,bb,bb,bb); }
            #pragma unroll 4
            for (int kq2 = 0; kq2 < 16; ++kq2)
                ro_step(out1, __ldg(&d_q1w2h[kq2*128 + c]), &bufB[8*kq2]);
            d_tmp[(n0+0)*128 + c] = d_mask[n0+0]*out0.x*out1.x;
            d_tmp[(n0+1)*128 + c] = d_mask[n0+1]*out0.y*out1.y;
            d_tmp[(n0+2)*128 + c] = d_mask[n0+2]*out0.z*out1.z;
            d_tmp[(n0+3)*128 + c] = d_mask[n0+3]*out0.w*out1.w;
        }
    }
    grid_barrier(4u*768u);

    // ---- final reduction: CTAs 0..15 ----
    if (blk < 16 && t < 128) {
        float s = 0.f;
        const float* tp = d_tmp + (size_t)blk*48*128 + t;
        #pragma unroll 8
        for (int jj = 0; jj < 48; ++jj)
            s += __ldcg(tp + jj*128);
        out[blk*128 + t] = 1.f/(1.f+expf(-s));
    }
}

extern "C" void kernel_launch(void* const* d_in, const int* in_sizes, int n_in,
                              void* d_out, int out_size) {
    const float* g       = (const float*)d_in[0];
    const float* h0      = (const float*)d_in[1];
    const float* e       = (const float*)d_in[2];
    const float* msg_w0  = (const float*)d_in[3];
    const float* msg_b0  = (const float*)d_in[4];
    const float* msg_w1  = (const float*)d_in[5];
    const float* msg_b1  = (const float*)d_in[6];
    const float* msg_w2  = (const float*)d_in[7];
    const float* msg_b2  = (const float*)d_in[8];
    const float* gru_wih = (const float*)d_in[9];
    const float* gru_whh = (const float*)d_in[10];
    const float* gru_bih = (const float*)d_in[11];
    const float* gru_bhh = (const float*)d_in[12];
    const float* r0_w0   = (const float*)d_in[13];
    const float* r0_b0   = (const float*)d_in[14];
    const float* r0_w1   = (const float*)d_in[15];
    const float* r0_b1   = (const float*)d_in[16];
    const float* r0_w2   = (const float*)d_in[17];
    const float* r0_b2   = (const float*)d_in[18];
    const float* r1_w0   = (const float*)d_in[19];
    const float* r1_b0   = (const float*)d_in[20];
    const float* r1_w1   = (const float*)d_in[21];
    const float* r1_b1   = (const float*)d_in[22];
    const float* r1_w2   = (const float*)d_in[23];
    const float* r1_b2   = (const float*)d_in[24];
    float* out = (float*)d_out;

    cudaFuncSetAttribute(relu2_kernel, cudaFuncAttributeMaxDynamicSharedMemorySize, RELU2_SMEM);

    megaprep_kernel<<<495, 192>>>(msg_w2, msg_b2, gru_wih, gru_whh, gru_bhh,
                                  msg_w1, msg_w0, h0, g,
                                  r0_w0, r0_w1, r0_w2, r1_w0, r1_w1, r1_w2);
    relu2_kernel<<<NE/128, 256, RELU2_SMEM>>>(e, msg_b0, msg_b1);
    megalayer_kernel<<<768, 192>>>(gru_bih, gru_bhh,
                                   r0_b0, r0_b1, r0_b2, r1_b0, r1_b1, r1_b2, out);
}